// round 1
// baseline (speedup 1.0000x reference)
#include <cuda_runtime.h>
#include <math.h>

// Problem constants
#define BATCH 8
#define CIN   256
#define MCH   256
#define OCH   256
#define HH    128
#define WW    128
#define HWPX  16384     // 128*128
#define KSEL  128       // top-k

// ---------- device scratch (static, allocation-free) ----------
__device__ float g_sel[(size_t)BATCH * KSEL * HWPX];          // relu(h)[:, :128], unmasked  (64MB)
__device__ float g_fused[(size_t)BATCH * 3 * KSEL * HWPX];    // dwconv outputs              (201MB)
__device__ float g_gap_part[BATCH * MCH * 128];               // per p-block partial sums of h
__device__ float g_gap2_part[BATCH * MCH * 128];              // per p-block partial sums of relu(h)
__device__ float g_w3[BATCH * KSEL * 9];
__device__ float g_w5[BATCH * KSEL * 25];
__device__ float g_w7[BATCH * KSEL * 49];

// =====================================================================
// K1: GEMM1  h[b,m,p] = sum_c x[b,c,p]*pw1_w[m,c] + pw1_b[m]
//     stores relu(h) for m<128, and deterministic per-block partial sums
//     of h (gap) and relu(h) (gap2) for all m.
// Tiles: BM=128 (m), BP=128 (pixels), BK=16. 256 threads, 8x8 microtile.
// =====================================================================
__global__ __launch_bounds__(256) void k1_gemm1(const float* __restrict__ x,
                                                const float* __restrict__ w,
                                                const float* __restrict__ bias)
{
    __shared__ float sA[16][128];   // [k][m]
    __shared__ float sB[16][128];   // [k][p]

    const int b  = blockIdx.z;
    const int m0 = blockIdx.y * 128;
    const int p0 = blockIdx.x * 128;
    const int t  = threadIdx.x;
    const int tx = t & 15;
    const int ty = t >> 4;

    const float* xb = x + (size_t)b * CIN * HWPX;

    float acc[8][8];
#pragma unroll
    for (int r = 0; r < 8; r++)
#pragma unroll
        for (int c = 0; c < 8; c++) acc[r][c] = 0.f;

    for (int k0 = 0; k0 < CIN; k0 += 16) {
#pragma unroll
        for (int i = t; i < 128 * 16; i += 256) {
            int m = i >> 4, kk = i & 15;
            sA[kk][m] = w[(m0 + m) * CIN + k0 + kk];
        }
#pragma unroll
        for (int i = t; i < 16 * 128; i += 256) {
            int kk = i >> 7, p = i & 127;
            sB[kk][p] = xb[(size_t)(k0 + kk) * HWPX + p0 + p];
        }
        __syncthreads();
#pragma unroll
        for (int kk = 0; kk < 16; kk++) {
            float ra[8], rb[8];
#pragma unroll
            for (int i = 0; i < 4; i++) {
                ra[i]     = sA[kk][ty * 4 + i];
                ra[4 + i] = sA[kk][64 + ty * 4 + i];
                rb[i]     = sB[kk][tx * 4 + i];
                rb[4 + i] = sB[kk][64 + tx * 4 + i];
            }
#pragma unroll
            for (int r = 0; r < 8; r++)
#pragma unroll
                for (int c = 0; c < 8; c++) acc[r][c] = fmaf(ra[r], rb[c], acc[r][c]);
        }
        __syncthreads();
    }

    int mrow[8], pcol[8];
#pragma unroll
    for (int i = 0; i < 4; i++) {
        mrow[i] = ty * 4 + i;  mrow[4 + i] = 64 + ty * 4 + i;
        pcol[i] = tx * 4 + i;  pcol[4 + i] = 64 + tx * 4 + i;
    }

    float gsum[8], g2sum[8];
#pragma unroll
    for (int r = 0; r < 8; r++) {
        float bv = bias[m0 + mrow[r]];
        float s1 = 0.f, s2 = 0.f;
#pragma unroll
        for (int c = 0; c < 8; c++) {
            float h  = acc[r][c] + bv;
            float hr = fmaxf(h, 0.f);
            s1 += h; s2 += hr;
            acc[r][c] = hr;
        }
        gsum[r] = s1; g2sum[r] = s2;
    }

    // store relu(h) for channels < 128 (blockIdx.y == 0 covers m 0..127)
    if (blockIdx.y == 0) {
#pragma unroll
        for (int r = 0; r < 8; r++) {
            size_t base = ((size_t)(b * KSEL + mrow[r])) * HWPX + p0;
            float4 v0 = make_float4(acc[r][0], acc[r][1], acc[r][2], acc[r][3]);
            float4 v1 = make_float4(acc[r][4], acc[r][5], acc[r][6], acc[r][7]);
            *(float4*)&g_sel[base + tx * 4]      = v0;
            *(float4*)&g_sel[base + 64 + tx * 4] = v1;
        }
    }

    // reduce over the 16 tx-threads holding the same m (lanes (ty&1)*16+tx)
#pragma unroll
    for (int off = 1; off < 16; off <<= 1) {
#pragma unroll
        for (int r = 0; r < 8; r++) {
            gsum[r]  += __shfl_xor_sync(0xffffffffu, gsum[r],  off);
            g2sum[r] += __shfl_xor_sync(0xffffffffu, g2sum[r], off);
        }
    }
    if (tx == 0) {
#pragma unroll
        for (int r = 0; r < 8; r++) {
            int gi = (b * MCH + m0 + mrow[r]) * 128 + blockIdx.x;
            g_gap_part[gi]  = gsum[r];
            g_gap2_part[gi] = g2sum[r];
        }
    }
}

// =====================================================================
// K2: finalize means, FC1/FC2, sigmoid, top-k mask (stable tie-break),
//     offsets, and per-(b,c) effective depthwise weights (mask folded in).
// One block per batch, 256 threads.
// =====================================================================
__global__ __launch_bounds__(256) void k2_scalar(const float* __restrict__ fc1_w,
                                                 const float* __restrict__ fc1_b,
                                                 const float* __restrict__ fc2_w,
                                                 const float* __restrict__ fc2_b,
                                                 const float* __restrict__ off_w,
                                                 const float* __restrict__ off_b,
                                                 const float* __restrict__ dw3,
                                                 const float* __restrict__ dw5,
                                                 const float* __restrict__ dw7)
{
    __shared__ float sgap[MCH], sgap2[MCH], shid[512], sscore[MCH];
    __shared__ float smask[KSEL], sscale[3], sshift[3];

    const int b = blockIdx.x;
    const int t = threadIdx.x;

    {   // deterministic reduction of per-block partials
        const float* p1 = g_gap_part  + (b * MCH + t) * 128;
        const float* p2 = g_gap2_part + (b * MCH + t) * 128;
        float s1 = 0.f, s2 = 0.f;
        for (int i = 0; i < 128; i++) { s1 += p1[i]; s2 += p2[i]; }
        sgap[t]  = s1 * (1.f / (float)HWPX);
        sgap2[t] = s2 * (1.f / (float)HWPX);
    }
    __syncthreads();

    for (int j = t; j < 512; j += 256) {
        float a = fc1_b[j];
        const float* wr = fc1_w + j * MCH;
        for (int c = 0; c < MCH; c++) a = fmaf(sgap[c], wr[c], a);
        shid[j] = fmaxf(a, 0.f);
    }
    __syncthreads();

    {
        float a = fc2_b[t];
        const float* wr = fc2_w + t * 512;
        for (int j = 0; j < 512; j++) a = fmaf(shid[j], wr[j], a);
        sscore[t] = 1.f / (1.f + expf(-a));
    }
    __syncthreads();

    if (t < KSEL) {          // mask only matters for channels < k
        float sc = sscore[t];
        int cnt = 0;
        for (int j = 0; j < MCH; j++) {
            float sj = sscore[j];
            cnt += (sj > sc) || (sj == sc && j < t);
        }
        smask[t] = (cnt < KSEL) ? 1.f : 0.f;
    }
    if (t >= 128 && t < 134) {
        int r = t - 128;
        float a = off_b[r];
        const float* wr = off_w + r * MCH;
        for (int c = 0; c < MCH; c++) a = fmaf(sgap2[c], wr[c], a);
        float o = tanhf(a);
        if ((r & 1) == 0) sscale[r >> 1] = 1.f / (1.f + expf(-o));
        else              sshift[r >> 1] = tanhf(o);
    }
    __syncthreads();

    for (int i = t; i < KSEL * 9; i += 256) {
        int c = i / 9, j = i % 9;
        g_w3[(b * KSEL + c) * 9 + j] = fmaf(dw3[c * 9 + j], 1.f + sscale[0], sshift[0]) * smask[c];
    }
    for (int i = t; i < KSEL * 25; i += 256) {
        int c = i / 25, j = i % 25;
        g_w5[(b * KSEL + c) * 25 + j] = fmaf(dw5[c * 25 + j], 1.f + sscale[1], sshift[1]) * smask[c];
    }
    for (int i = t; i < KSEL * 49; i += 256) {
        int c = i / 49, j = i % 49;
        g_w7[(b * KSEL + c) * 49 + j] = fmaf(dw7[c * 49 + j], 1.f + sscale[2], sshift[2]) * smask[c];
    }
}

// =====================================================================
// K3: depthwise 3x3 + 5x5 + 7x7 in one pass per (b,c) channel.
// 32x32 output tiles with halo-3 smem staging. grid (16, 128, 8).
// =====================================================================
__global__ __launch_bounds__(256) void k3_dwconv()
{
    __shared__ float s[38][38];
    __shared__ float sw[84];

    const int b = blockIdx.z;
    const int c = blockIdx.y;
    const int tile = blockIdx.x;
    const int ty0 = (tile >> 2) * 32;
    const int tx0 = (tile & 3) * 32;
    const int t = threadIdx.x;

    const float* in = g_sel + ((size_t)(b * KSEL + c)) * HWPX;

    for (int i = t; i < 38 * 38; i += 256) {
        int r = i / 38, cc = i % 38;
        int gy = ty0 + r - 3, gx = tx0 + cc - 3;
        s[r][cc] = (gy >= 0 && gy < HH && gx >= 0 && gx < WW) ? in[gy * WW + gx] : 0.f;
    }
    if (t < 9)        sw[t] = g_w3[(b * KSEL + c) * 9 + t];
    else if (t < 34)  sw[t] = g_w5[(b * KSEL + c) * 25 + (t - 9)];
    else if (t < 83)  sw[t] = g_w7[(b * KSEL + c) * 49 + (t - 34)];
    __syncthreads();

    for (int i = t; i < 1024; i += 256) {
        int py = i >> 5, px = i & 31;
        float a3 = 0.f, a5 = 0.f, a7 = 0.f;
#pragma unroll
        for (int dy = -3; dy <= 3; dy++) {
#pragma unroll
            for (int dx = -3; dx <= 3; dx++) {
                float v = s[py + 3 + dy][px + 3 + dx];
                a7 = fmaf(sw[34 + (dy + 3) * 7 + (dx + 3)], v, a7);
                if (dy >= -2 && dy <= 2 && dx >= -2 && dx <= 2)
                    a5 = fmaf(sw[9 + (dy + 2) * 5 + (dx + 2)], v, a5);
                if (dy >= -1 && dy <= 1 && dx >= -1 && dx <= 1)
                    a3 = fmaf(sw[(dy + 1) * 3 + (dx + 1)], v, a3);
            }
        }
        size_t o = ((size_t)(b * (3 * KSEL) + c)) * HWPX + (ty0 + py) * WW + tx0 + px;
        g_fused[o]                         = a3;
        g_fused[o + (size_t)KSEL * HWPX]   = a5;
        g_fused[o + (size_t)2 * KSEL * HWPX] = a7;
    }
}

// =====================================================================
// K4: GEMM2  out[b,o,p] = sum_{q<384} pw_w[o,q]*fused[b,q,p] + pw_b[o] + x[b,o,p]
// pw_w row stride is 768 (we use the first 384 columns). Same tiling as K1.
// =====================================================================
__global__ __launch_bounds__(256) void k4_gemm2(const float* __restrict__ w,
                                                const float* __restrict__ bias,
                                                const float* __restrict__ x,
                                                float* __restrict__ out)
{
    __shared__ float sA[16][128];
    __shared__ float sB[16][128];

    const int b  = blockIdx.z;
    const int o0 = blockIdx.y * 128;
    const int p0 = blockIdx.x * 128;
    const int t  = threadIdx.x;
    const int tx = t & 15;
    const int ty = t >> 4;

    const float* fb = g_fused + (size_t)b * (3 * KSEL) * HWPX;

    float acc[8][8];
#pragma unroll
    for (int r = 0; r < 8; r++)
#pragma unroll
        for (int c = 0; c < 8; c++) acc[r][c] = 0.f;

    for (int k0 = 0; k0 < 3 * KSEL; k0 += 16) {
#pragma unroll
        for (int i = t; i < 128 * 16; i += 256) {
            int m = i >> 4, kk = i & 15;
            sA[kk][m] = w[(o0 + m) * 768 + k0 + kk];
        }
#pragma unroll
        for (int i = t; i < 16 * 128; i += 256) {
            int kk = i >> 7, p = i & 127;
            sB[kk][p] = fb[(size_t)(k0 + kk) * HWPX + p0 + p];
        }
        __syncthreads();
#pragma unroll
        for (int kk = 0; kk < 16; kk++) {
            float ra[8], rb[8];
#pragma unroll
            for (int i = 0; i < 4; i++) {
                ra[i]     = sA[kk][ty * 4 + i];
                ra[4 + i] = sA[kk][64 + ty * 4 + i];
                rb[i]     = sB[kk][tx * 4 + i];
                rb[4 + i] = sB[kk][64 + tx * 4 + i];
            }
#pragma unroll
            for (int r = 0; r < 8; r++)
#pragma unroll
                for (int c = 0; c < 8; c++) acc[r][c] = fmaf(ra[r], rb[c], acc[r][c]);
        }
        __syncthreads();
    }

#pragma unroll
    for (int half = 0; half < 2; half++) {
#pragma unroll
        for (int i = 0; i < 4; i++) {
            int m = half * 64 + ty * 4 + i;
            float bv = bias[o0 + m];
            size_t base = ((size_t)(b * OCH + o0 + m)) * HWPX + p0;
            int r = half * 4 + i;
#pragma unroll
            for (int ph = 0; ph < 2; ph++) {
                int pc = ph * 64 + tx * 4;
                float4 xr = *(const float4*)&x[base + pc];
                float4 v;
                v.x = acc[r][ph * 4 + 0] + bv + xr.x;
                v.y = acc[r][ph * 4 + 1] + bv + xr.y;
                v.z = acc[r][ph * 4 + 2] + bv + xr.z;
                v.w = acc[r][ph * 4 + 3] + bv + xr.w;
                *(float4*)&out[base + pc] = v;
            }
        }
    }
}

// =====================================================================
extern "C" void kernel_launch(void* const* d_in, const int* in_sizes, int n_in,
                              void* d_out, int out_size)
{
    const float* x     = (const float*)d_in[0];
    const float* pw1_w = (const float*)d_in[1];
    const float* pw1_b = (const float*)d_in[2];
    const float* fc1_w = (const float*)d_in[3];
    const float* fc1_b = (const float*)d_in[4];
    const float* fc2_w = (const float*)d_in[5];
    const float* fc2_b = (const float*)d_in[6];
    const float* off_w = (const float*)d_in[7];
    const float* off_b = (const float*)d_in[8];
    const float* dw3   = (const float*)d_in[9];
    const float* dw5   = (const float*)d_in[10];
    const float* dw7   = (const float*)d_in[11];
    const float* pw_w  = (const float*)d_in[12];
    const float* pw_b  = (const float*)d_in[13];
    float* out = (float*)d_out;

    k1_gemm1<<<dim3(128, 2, BATCH), 256>>>(x, pw1_w, pw1_b);
    k2_scalar<<<BATCH, 256>>>(fc1_w, fc1_b, fc2_w, fc2_b, off_w, off_b, dw3, dw5, dw7);
    k3_dwconv<<<dim3(16, KSEL, BATCH), 256>>>();
    k4_gemm2<<<dim3(128, 2, BATCH), 256>>>(pw_w, pw_b, x, out);
}

// round 4
// speedup vs baseline: 2.4664x; 2.4664x over previous
#include <cuda_runtime.h>
#include <cuda_bf16.h>
#include <cstdint>
#include <math.h>

#define BATCH 8
#define CIN   256
#define MCH   256
#define OCH   256
#define HH    128
#define WW    128
#define HWPX  16384
#define KSEL  128

// ---------------- device scratch ----------------
__device__ __align__(128) __nv_bfloat16 gXb[(size_t)BATCH * CIN * HWPX];           // x bf16
__device__ __align__(128) __nv_bfloat16 g_selb[(size_t)BATCH * KSEL * HWPX];       // relu(h)[:,:128] bf16
__device__ __align__(128) __nv_bfloat16 g_fusedb[(size_t)BATCH * 3 * KSEL * HWPX]; // dwconv out bf16
__device__ __align__(128) __nv_bfloat16 gA1[2 * 128 * 256];                        // pw1_w bf16 linear
__device__ __align__(128) __nv_bfloat16 gA2[2 * 128 * 384];                        // pw_w[:, :384] bf16 linear
__device__ float gXmean[BATCH * CIN];
__device__ float g_gap2_part[BATCH * MCH * 128];
__device__ float g_w3[BATCH * KSEL * 9];
__device__ float g_w5[BATCH * KSEL * 25];
__device__ float g_w7[BATCH * KSEL * 49];

// ---------------- PTX helpers (baseline compute_103 features only) ----------------
__device__ __forceinline__ uint32_t smem_u32(const void* p) {
    uint32_t a;
    asm("{ .reg .u64 t; cvta.to.shared.u64 t, %1; cvt.u32.u64 %0, t; }" : "=r"(a) : "l"(p));
    return a;
}
__device__ __forceinline__ void cp16(uint32_t dst, const void* src) {
    asm volatile("cp.async.cg.shared.global [%0], [%1], 16;" :: "r"(dst), "l"(src) : "memory");
}
__device__ __forceinline__ void cp_commit() { asm volatile("cp.async.commit_group;" ::: "memory"); }
template<int N> __device__ __forceinline__ void cp_wait() { asm volatile("cp.async.wait_group %0;" :: "n"(N) : "memory"); }

__device__ __forceinline__ void ldsm_x4(uint32_t* r, uint32_t addr) {
    asm volatile("ldmatrix.sync.aligned.m8n8.x4.shared.b16 {%0,%1,%2,%3}, [%4];"
                 : "=r"(r[0]), "=r"(r[1]), "=r"(r[2]), "=r"(r[3]) : "r"(addr));
}
__device__ __forceinline__ void ldsm_x4_t(uint32_t* r, uint32_t addr) {
    asm volatile("ldmatrix.sync.aligned.m8n8.x4.trans.shared.b16 {%0,%1,%2,%3}, [%4];"
                 : "=r"(r[0]), "=r"(r[1]), "=r"(r[2]), "=r"(r[3]) : "r"(addr));
}
__device__ __forceinline__ void mma16816(float* d, const uint32_t* a, const uint32_t* b) {
    asm volatile("mma.sync.aligned.m16n8k16.row.col.f32.bf16.bf16.f32 "
                 "{%0,%1,%2,%3}, {%4,%5,%6,%7}, {%8,%9}, {%0,%1,%2,%3};"
                 : "+f"(d[0]), "+f"(d[1]), "+f"(d[2]), "+f"(d[3])
                 : "r"(a[0]), "r"(a[1]), "r"(a[2]), "r"(a[3]), "r"(b[0]), "r"(b[1]));
}

// =====================================================================
// kxc: x fp32 -> bf16 + exact fp32 row means (score path stays exact)
// =====================================================================
__global__ __launch_bounds__(256) void kxc(const float* __restrict__ x)
{
    __shared__ float red[256];
    const int row = blockIdx.x;
    const int t = threadIdx.x;
    const float4* in4 = (const float4*)(x + (size_t)row * HWPX);
    __nv_bfloat162* ob = (__nv_bfloat162*)(gXb + (size_t)row * HWPX);
    float s = 0.f;
#pragma unroll
    for (int it = 0; it < 16; it++) {
        int j = t + it * 256;
        float4 v = in4[j];
        s += v.x + v.y + v.z + v.w;
        ob[j * 2 + 0] = __floats2bfloat162_rn(v.x, v.y);
        ob[j * 2 + 1] = __floats2bfloat162_rn(v.z, v.w);
    }
    red[t] = s;
    __syncthreads();
    for (int o = 128; o > 0; o >>= 1) {
        if (t < o) red[t] += red[t + o];
        __syncthreads();
    }
    if (t == 0) gXmean[row] = red[0] * (1.f / (float)HWPX);
}

// =====================================================================
// kprep: weights -> bf16 linear row-major images
// =====================================================================
__global__ __launch_bounds__(256) void kprep(const float* __restrict__ pw1_w,
                                             const float* __restrict__ pw_w)
{
    int i = blockIdx.x * 256 + threadIdx.x;
    if (i < 65536) {
        gA1[i] = __float2bfloat16(pw1_w[i]);
    } else {
        int j = i - 65536;            // 256 rows x 384 cols
        int m = j / 384, k = j % 384;
        gA2[j] = __float2bfloat16(pw_w[m * 768 + k]);
    }
}

// =====================================================================
// kgemm<KDIM, EP>: mma.sync bf16 GEMM. CTA 128m x 128p, 8 warps (2x4),
// warp tile 64m x 32p. A full-K in smem, B double-buffered KC=64 chunks.
// EP=1: +bias, relu, bf16 sel store (MT==0), deterministic gap2 partials.
// EP=2: +bias +residual, fp32 out.
// grid (128, 2, BATCH), 256 threads.
// =====================================================================
template<int KDIM, int EP>
__global__ __launch_bounds__(256, 1)
void kgemm(const __nv_bfloat16* __restrict__ Aimg,
           const __nv_bfloat16* __restrict__ Bsrc,
           const float* __restrict__ bias,
           const float* __restrict__ xres,
           float* __restrict__ out)
{
    constexpr int KC = 64;
    constexpr int NCHUNK = KDIM / KC;
    constexpr int ASZ = 128 * KDIM * 2;      // bytes
    constexpr int BROW = 256;                // bytes per B k-row (128 bf16)
    constexpr int BSZ = KC * BROW;           // 16KB per buffer

    extern __shared__ char sraw[];
    const uint32_t rawu = smem_u32(sraw);
    const uint32_t sbase = (rawu + 127u) & ~127u;
    const uint32_t uA = sbase;
    const uint32_t uB = sbase + ASZ;
    float* sg = (float*)(sraw + (sbase - rawu) + ASZ + 2 * BSZ);   // [4][128] (EP1)

    const int t = threadIdx.x, wid = t >> 5, lane = t & 31;
    const int b = blockIdx.z, MT = blockIdx.y, pc = blockIdx.x;
    const int m0 = MT * 128;
    const int p0 = pc * 128;
    const int wm = (wid >> 2) * 64;          // warp m offset in tile
    const int wp = (wid & 3) * 32;           // warp p offset in tile

    const char* Bb = (const char*)(Bsrc + (size_t)b * KDIM * HWPX);
    const char* Ab = (const char*)(Aimg + (size_t)MT * 128 * KDIM);

    // ---- A load (swizzled), full K ----
    {
        constexpr int CPR = KDIM / 8;        // 16B chunks per row
#pragma unroll
        for (int i = t; i < 128 * CPR; i += 256) {
            int m = i / CPR, j = i % CPR;
            cp16(uA + m * (KDIM * 2) + ((j * 16) ^ ((m & 7) << 4)),
                 Ab + (size_t)m * (KDIM * 2) + j * 16);
        }
    }
    // ---- B chunk loader ----
    auto loadB = [&](int buf, int kc0) {
        uint32_t dst = uB + buf * BSZ;
#pragma unroll
        for (int i = t; i < KC * 16; i += 256) {
            int k = i >> 4, j = i & 15;
            cp16(dst + k * BROW + ((j * 16) ^ ((k & 7) << 4)),
                 Bb + ((size_t)(kc0 + k) * HWPX + p0) * 2 + j * 16);
        }
    };
    loadB(0, 0);
    cp_commit();                 // group0: A + B0
    if (NCHUNK > 1) { loadB(1, KC); cp_commit(); }

    float acc[4][4][4];
#pragma unroll
    for (int mi = 0; mi < 4; mi++)
#pragma unroll
        for (int ni = 0; ni < 4; ni++)
#pragma unroll
            for (int r = 0; r < 4; r++) acc[mi][ni][r] = 0.f;

    // precomputed lane addresses
    const int a_m  = wm + (lane & 15);
    const int a_kb = (lane >> 4) * 16;                 // byte offset for k-half
    const uint32_t aBase = uA + a_m * (KDIM * 2);
    const uint32_t aSwz  = (a_m & 7) << 4;
    const int b_k  = lane & 15;
    const int b_nb = wp * 2 + (lane >> 4) * 16;        // byte offset of n within row
    const uint32_t bSwzK = (b_k & 7) << 4;

    for (int c = 0; c < NCHUNK; c++) {
        // RACE FIX (R4): on the final chunk the only outstanding group is the
        // one holding this chunk's data — wait_group<1> would allow it to still
        // be in flight. Drain fully on the last iteration.
        if (c == NCHUNK - 1) cp_wait<0>(); else cp_wait<1>();
        __syncthreads();
        const uint32_t bb = uB + (c & 1) * BSZ + b_k * BROW;
#pragma unroll
        for (int ks = 0; ks < KC / 16; ks++) {
            const int kB = ks * 32;                    // byte offset of k within A row chunk
            uint32_t a[4][4];
#pragma unroll
            for (int mi = 0; mi < 4; mi++)
                ldsm_x4(a[mi], aBase + mi * 16 * (KDIM * 2) +
                               (((c * KC * 2) + kB + a_kb) ^ aSwz));
            uint32_t bf[2][4];
#pragma unroll
            for (int h = 0; h < 2; h++)
                ldsm_x4_t(bf[h], bb + ks * 16 * BROW + ((b_nb + h * 32) ^ bSwzK));
#pragma unroll
            for (int mi = 0; mi < 4; mi++)
#pragma unroll
                for (int ni = 0; ni < 4; ni++)
                    mma16816(acc[mi][ni], a[mi], &bf[ni >> 1][(ni & 1) * 2]);
        }
        __syncthreads();
        if (c + 2 < NCHUNK) { loadB(c & 1, (c + 2) * KC); cp_commit(); }
    }

    // ---- epilogue ----
    const int erow = lane >> 2;
    const int ecol = (lane & 3) * 2;
    if (EP == 2) {
#pragma unroll
        for (int mi = 0; mi < 4; mi++) {
#pragma unroll
            for (int h = 0; h < 2; h++) {
                const int m = wm + mi * 16 + h * 8 + erow;
                const float bv = bias[m0 + m];
                const size_t rb = ((size_t)(b * OCH + m0 + m)) * HWPX + p0;
#pragma unroll
                for (int ni = 0; ni < 4; ni++) {
                    const size_t o = rb + wp + ni * 8 + ecol;
                    float2 xr = *(const float2*)&xres[o];
                    float2 v;
                    v.x = acc[mi][ni][2 * h]     + bv + xr.x;
                    v.y = acc[mi][ni][2 * h + 1] + bv + xr.y;
                    *(float2*)&out[o] = v;
                }
            }
        }
    } else {
        float rs[4][2];
#pragma unroll
        for (int mi = 0; mi < 4; mi++) {
#pragma unroll
            for (int h = 0; h < 2; h++) {
                const int m = wm + mi * 16 + h * 8 + erow;
                const float bv = bias[m0 + m];
                float s2 = 0.f;
#pragma unroll
                for (int ni = 0; ni < 4; ni++) {
                    float v0 = fmaxf(acc[mi][ni][2 * h]     + bv, 0.f);
                    float v1 = fmaxf(acc[mi][ni][2 * h + 1] + bv, 0.f);
                    s2 += v0 + v1;
                    if (MT == 0) {
                        size_t o = ((size_t)(b * KSEL + m)) * HWPX + p0 + wp + ni * 8 + ecol;
                        *(__nv_bfloat162*)&g_selb[o] = __floats2bfloat162_rn(v0, v1);
                    }
                }
                rs[mi][h] = s2;
            }
        }
        // reduce over the 4 lanes sharing a row (lane%4)
#pragma unroll
        for (int mi = 0; mi < 4; mi++)
#pragma unroll
            for (int h = 0; h < 2; h++) {
                rs[mi][h] += __shfl_xor_sync(0xffffffffu, rs[mi][h], 1);
                rs[mi][h] += __shfl_xor_sync(0xffffffffu, rs[mi][h], 2);
            }
        if ((lane & 3) == 0) {
#pragma unroll
            for (int mi = 0; mi < 4; mi++)
#pragma unroll
                for (int h = 0; h < 2; h++)
                    sg[(wid & 3) * 128 + wm + mi * 16 + h * 8 + erow] = rs[mi][h];
        }
        __syncthreads();
        if (t < 128)
            g_gap2_part[(b * MCH + m0 + t) * 128 + pc] =
                sg[t] + sg[128 + t] + sg[256 + t] + sg[384 + t];
    }
}

// =====================================================================
// k2: exact fp32 gap (from xmean), FCs, sigmoid, top-k mask, offsets,
//     effective depthwise weights (mask folded in)
// =====================================================================
__global__ __launch_bounds__(256) void k2_scalar(const float* __restrict__ pw1_w,
                                                 const float* __restrict__ pw1_b,
                                                 const float* __restrict__ fc1_w,
                                                 const float* __restrict__ fc1_b,
                                                 const float* __restrict__ fc2_w,
                                                 const float* __restrict__ fc2_b,
                                                 const float* __restrict__ off_w,
                                                 const float* __restrict__ off_b,
                                                 const float* __restrict__ dw3,
                                                 const float* __restrict__ dw5,
                                                 const float* __restrict__ dw7)
{
    __shared__ float sgap[MCH], sgap2[MCH], shid[512], sscore[MCH];
    __shared__ float smask[KSEL], sscale[3], sshift[3];

    const int b = blockIdx.x;
    const int t = threadIdx.x;

    {
        float a = pw1_b[t];
        const float* wr = pw1_w + t * CIN;
        const float* xm = gXmean + b * CIN;
        for (int c = 0; c < CIN; c++) a = fmaf(xm[c], wr[c], a);
        sgap[t] = a;
        const float* p2 = g_gap2_part + (b * MCH + t) * 128;
        float s2 = 0.f;
        for (int i = 0; i < 128; i++) s2 += p2[i];
        sgap2[t] = s2 * (1.f / (float)HWPX);
    }
    __syncthreads();

    for (int j = t; j < 512; j += 256) {
        float a = fc1_b[j];
        const float* wr = fc1_w + j * MCH;
        for (int c = 0; c < MCH; c++) a = fmaf(sgap[c], wr[c], a);
        shid[j] = fmaxf(a, 0.f);
    }
    __syncthreads();

    {
        float a = fc2_b[t];
        const float* wr = fc2_w + t * 512;
        for (int j = 0; j < 512; j++) a = fmaf(shid[j], wr[j], a);
        sscore[t] = 1.f / (1.f + expf(-a));
    }
    __syncthreads();

    if (t < KSEL) {
        float sc = sscore[t];
        int cnt = 0;
        for (int j = 0; j < MCH; j++) {
            float sj = sscore[j];
            cnt += (sj > sc) || (sj == sc && j < t);
        }
        smask[t] = (cnt < KSEL) ? 1.f : 0.f;
    }
    if (t >= 128 && t < 134) {
        int r = t - 128;
        float a = off_b[r];
        const float* wr = off_w + r * MCH;
        for (int c = 0; c < MCH; c++) a = fmaf(sgap2[c], wr[c], a);
        float o = tanhf(a);
        if ((r & 1) == 0) sscale[r >> 1] = 1.f / (1.f + expf(-o));
        else              sshift[r >> 1] = tanhf(o);
    }
    __syncthreads();

    for (int i = t; i < KSEL * 9; i += 256) {
        int c = i / 9, j = i % 9;
        g_w3[(b * KSEL + c) * 9 + j] = fmaf(dw3[c * 9 + j], 1.f + sscale[0], sshift[0]) * smask[c];
    }
    for (int i = t; i < KSEL * 25; i += 256) {
        int c = i / 25, j = i % 25;
        g_w5[(b * KSEL + c) * 25 + j] = fmaf(dw5[c * 25 + j], 1.f + sscale[1], sshift[1]) * smask[c];
    }
    for (int i = t; i < KSEL * 49; i += 256) {
        int c = i / 49, j = i % 49;
        g_w7[(b * KSEL + c) * 49 + j] = fmaf(dw7[c * 49 + j], 1.f + sscale[2], sshift[2]) * smask[c];
    }
}

// =====================================================================
// k3: fused depthwise 3x3+5x5+7x7, bf16 in/out, fp32 compute
// =====================================================================
__global__ __launch_bounds__(256) void k3_dwconv()
{
    __shared__ float s[38][38];
    __shared__ float sw[84];

    const int b = blockIdx.z;
    const int c = blockIdx.y;
    const int tile = blockIdx.x;
    const int ty0 = (tile >> 2) * 32;
    const int tx0 = (tile & 3) * 32;
    const int t = threadIdx.x;

    const __nv_bfloat16* in = g_selb + ((size_t)(b * KSEL + c)) * HWPX;

    for (int i = t; i < 38 * 38; i += 256) {
        int r = i / 38, cc = i % 38;
        int gy = ty0 + r - 3, gx = tx0 + cc - 3;
        s[r][cc] = (gy >= 0 && gy < HH && gx >= 0 && gx < WW) ? __bfloat162float(in[gy * WW + gx]) : 0.f;
    }
    if (t < 9)        sw[t] = g_w3[(b * KSEL + c) * 9 + t];
    else if (t < 34)  sw[t] = g_w5[(b * KSEL + c) * 25 + (t - 9)];
    else if (t < 83)  sw[t] = g_w7[(b * KSEL + c) * 49 + (t - 34)];
    __syncthreads();

    for (int i = t; i < 1024; i += 256) {
        int py = i >> 5, px = i & 31;
        float a3 = 0.f, a5 = 0.f, a7 = 0.f;
#pragma unroll
        for (int dy = -3; dy <= 3; dy++) {
#pragma unroll
            for (int dx = -3; dx <= 3; dx++) {
                float v = s[py + 3 + dy][px + 3 + dx];
                a7 = fmaf(sw[34 + (dy + 3) * 7 + (dx + 3)], v, a7);
                if (dy >= -2 && dy <= 2 && dx >= -2 && dx <= 2)
                    a5 = fmaf(sw[9 + (dy + 2) * 5 + (dx + 2)], v, a5);
                if (dy >= -1 && dy <= 1 && dx >= -1 && dx <= 1)
                    a3 = fmaf(sw[(dy + 1) * 3 + (dx + 1)], v, a3);
            }
        }
        size_t o = ((size_t)(b * (3 * KSEL) + c)) * HWPX + (ty0 + py) * WW + tx0 + px;
        g_fusedb[o]                           = __float2bfloat16(a3);
        g_fusedb[o + (size_t)KSEL * HWPX]     = __float2bfloat16(a5);
        g_fusedb[o + (size_t)2 * KSEL * HWPX] = __float2bfloat16(a7);
    }
}

// =====================================================================
extern "C" void kernel_launch(void* const* d_in, const int* in_sizes, int n_in,
                              void* d_out, int out_size)
{
    const float* x     = (const float*)d_in[0];
    const float* pw1_w = (const float*)d_in[1];
    const float* pw1_b = (const float*)d_in[2];
    const float* fc1_w = (const float*)d_in[3];
    const float* fc1_b = (const float*)d_in[4];
    const float* fc2_w = (const float*)d_in[5];
    const float* fc2_b = (const float*)d_in[6];
    const float* off_w = (const float*)d_in[7];
    const float* off_b = (const float*)d_in[8];
    const float* dw3   = (const float*)d_in[9];
    const float* dw5   = (const float*)d_in[10];
    const float* dw7   = (const float*)d_in[11];
    const float* pw_w  = (const float*)d_in[12];
    const float* pw_b  = (const float*)d_in[13];
    float* out = (float*)d_out;

    const int smem1 = 128 * 256 * 2 + 2 * 64 * 256 + 4 * 128 * 4 + 256;   // ~100KB
    const int smem2 = 128 * 384 * 2 + 2 * 64 * 256 + 4 * 128 * 4 + 256;   // ~132KB
    cudaFuncSetAttribute((const void*)kgemm<256, 1>, cudaFuncAttributeMaxDynamicSharedMemorySize, smem1);
    cudaFuncSetAttribute((const void*)kgemm<384, 2>, cudaFuncAttributeMaxDynamicSharedMemorySize, smem2);

    __nv_bfloat16 *gA1p, *gA2p, *gXbp, *gFbp;
    cudaGetSymbolAddress((void**)&gA1p, gA1);
    cudaGetSymbolAddress((void**)&gA2p, gA2);
    cudaGetSymbolAddress((void**)&gXbp, gXb);
    cudaGetSymbolAddress((void**)&gFbp, g_fusedb);

    kxc<<<BATCH * CIN, 256>>>(x);
    kprep<<<640, 256>>>(pw1_w, pw_w);
    kgemm<256, 1><<<dim3(128, 2, BATCH), 256, smem1>>>(gA1p, gXbp, pw1_b, nullptr, nullptr);
    k2_scalar<<<BATCH, 256>>>(pw1_w, pw1_b, fc1_w, fc1_b, fc2_w, fc2_b, off_w, off_b, dw3, dw5, dw7);
    k3_dwconv<<<dim3(16, KSEL, BATCH), 256>>>();
    kgemm<384, 2><<<dim3(128, 2, BATCH), 256, smem2>>>(gA2p, gFbp, pw_b, x, out);
}

// round 5
// speedup vs baseline: 2.7139x; 1.1003x over previous
#include <cuda_runtime.h>
#include <cuda_bf16.h>
#include <cstdint>
#include <math.h>

#define BATCH 8
#define CIN   256
#define MCH   256
#define OCH   256
#define HH    128
#define WW    128
#define HWPX  16384
#define KSEL  128

// ---------------- device scratch ----------------
__device__ __align__(128) __nv_bfloat16 gXb[(size_t)BATCH * CIN * HWPX];           // x bf16
__device__ __align__(128) __nv_bfloat16 g_selb[(size_t)BATCH * KSEL * HWPX];       // relu(h)[:,:128] bf16
__device__ __align__(128) __nv_bfloat16 g_fusedb[(size_t)BATCH * 3 * KSEL * HWPX]; // dwconv out bf16
__device__ __align__(128) __nv_bfloat16 gA1[2 * 128 * 256];                        // pw1_w bf16 linear
__device__ __align__(128) __nv_bfloat16 gA2[2 * 128 * 384];                        // pw_w[:, :384] bf16 linear
__device__ float gXmean[BATCH * CIN];
__device__ float g_gap2_part[BATCH * MCH * 128];
__device__ float g_w3[BATCH * KSEL * 9];
__device__ float g_w5[BATCH * KSEL * 25];
__device__ float g_w7[BATCH * KSEL * 49];

// ---------------- PTX helpers (baseline compute_103 features only) ----------------
__device__ __forceinline__ uint32_t smem_u32(const void* p) {
    uint32_t a;
    asm("{ .reg .u64 t; cvta.to.shared.u64 t, %1; cvt.u32.u64 %0, t; }" : "=r"(a) : "l"(p));
    return a;
}
__device__ __forceinline__ void cp16(uint32_t dst, const void* src) {
    asm volatile("cp.async.cg.shared.global [%0], [%1], 16;" :: "r"(dst), "l"(src) : "memory");
}
__device__ __forceinline__ void cp_commit() { asm volatile("cp.async.commit_group;" ::: "memory"); }
template<int N> __device__ __forceinline__ void cp_wait() { asm volatile("cp.async.wait_group %0;" :: "n"(N) : "memory"); }

__device__ __forceinline__ void ldsm_x4(uint32_t* r, uint32_t addr) {
    asm volatile("ldmatrix.sync.aligned.m8n8.x4.shared.b16 {%0,%1,%2,%3}, [%4];"
                 : "=r"(r[0]), "=r"(r[1]), "=r"(r[2]), "=r"(r[3]) : "r"(addr));
}
__device__ __forceinline__ void ldsm_x4_t(uint32_t* r, uint32_t addr) {
    asm volatile("ldmatrix.sync.aligned.m8n8.x4.trans.shared.b16 {%0,%1,%2,%3}, [%4];"
                 : "=r"(r[0]), "=r"(r[1]), "=r"(r[2]), "=r"(r[3]) : "r"(addr));
}
__device__ __forceinline__ void mma16816(float* d, const uint32_t* a, const uint32_t* b) {
    asm volatile("mma.sync.aligned.m16n8k16.row.col.f32.bf16.bf16.f32 "
                 "{%0,%1,%2,%3}, {%4,%5,%6,%7}, {%8,%9}, {%0,%1,%2,%3};"
                 : "+f"(d[0]), "+f"(d[1]), "+f"(d[2]), "+f"(d[3])
                 : "r"(a[0]), "r"(a[1]), "r"(a[2]), "r"(a[3]), "r"(b[0]), "r"(b[1]));
}
__device__ __forceinline__ float wred(float v) {
    v += __shfl_xor_sync(0xffffffffu, v, 16);
    v += __shfl_xor_sync(0xffffffffu, v, 8);
    v += __shfl_xor_sync(0xffffffffu, v, 4);
    v += __shfl_xor_sync(0xffffffffu, v, 2);
    v += __shfl_xor_sync(0xffffffffu, v, 1);
    return v;
}

// =====================================================================
// kxc: x fp32 -> bf16 + exact fp32 row means (score path stays exact)
// =====================================================================
__global__ __launch_bounds__(256) void kxc(const float* __restrict__ x)
{
    __shared__ float red[256];
    const int row = blockIdx.x;
    const int t = threadIdx.x;
    const float4* in4 = (const float4*)(x + (size_t)row * HWPX);
    __nv_bfloat162* ob = (__nv_bfloat162*)(gXb + (size_t)row * HWPX);
    float s = 0.f;
#pragma unroll
    for (int it = 0; it < 16; it++) {
        int j = t + it * 256;
        float4 v = in4[j];
        s += v.x + v.y + v.z + v.w;
        ob[j * 2 + 0] = __floats2bfloat162_rn(v.x, v.y);
        ob[j * 2 + 1] = __floats2bfloat162_rn(v.z, v.w);
    }
    red[t] = s;
    __syncthreads();
    for (int o = 128; o > 0; o >>= 1) {
        if (t < o) red[t] += red[t + o];
        __syncthreads();
    }
    if (t == 0) gXmean[row] = red[0] * (1.f / (float)HWPX);
}

// =====================================================================
// kprep: weights -> bf16 linear row-major images
// =====================================================================
__global__ __launch_bounds__(256) void kprep(const float* __restrict__ pw1_w,
                                             const float* __restrict__ pw_w)
{
    int i = blockIdx.x * 256 + threadIdx.x;
    if (i < 65536) {
        gA1[i] = __float2bfloat16(pw1_w[i]);
    } else {
        int j = i - 65536;            // 256 rows x 384 cols
        int m = j / 384, k = j % 384;
        gA2[j] = __float2bfloat16(pw_w[m * 768 + k]);
    }
}

// =====================================================================
// kgemm<KDIM, EP>: mma.sync bf16 GEMM. CTA 128m x 128p, 8 warps (2x4),
// warp tile 64m x 32p. A full-K in smem, B double-buffered KC=64 chunks.
// EP=1: +bias, relu, bf16 sel store (MT==0), deterministic gap2 partials.
// EP=2: +bias +residual, fp32 out.
// grid (128, 2, BATCH), 256 threads.
// =====================================================================
template<int KDIM, int EP>
__global__ __launch_bounds__(256, 1)
void kgemm(const __nv_bfloat16* __restrict__ Aimg,
           const __nv_bfloat16* __restrict__ Bsrc,
           const float* __restrict__ bias,
           const float* __restrict__ xres,
           float* __restrict__ out)
{
    constexpr int KC = 64;
    constexpr int NCHUNK = KDIM / KC;
    constexpr int ASZ = 128 * KDIM * 2;      // bytes
    constexpr int BROW = 256;                // bytes per B k-row (128 bf16)
    constexpr int BSZ = KC * BROW;           // 16KB per buffer

    extern __shared__ char sraw[];
    const uint32_t rawu = smem_u32(sraw);
    const uint32_t sbase = (rawu + 127u) & ~127u;
    const uint32_t uA = sbase;
    const uint32_t uB = sbase + ASZ;
    float* sg = (float*)(sraw + (sbase - rawu) + ASZ + 2 * BSZ);   // [4][128] (EP1)

    const int t = threadIdx.x, wid = t >> 5, lane = t & 31;
    const int b = blockIdx.z, MT = blockIdx.y, pc = blockIdx.x;
    const int m0 = MT * 128;
    const int p0 = pc * 128;
    const int wm = (wid >> 2) * 64;          // warp m offset in tile
    const int wp = (wid & 3) * 32;           // warp p offset in tile

    const char* Bb = (const char*)(Bsrc + (size_t)b * KDIM * HWPX);
    const char* Ab = (const char*)(Aimg + (size_t)MT * 128 * KDIM);

    // ---- A load (swizzled), full K ----
    {
        constexpr int CPR = KDIM / 8;        // 16B chunks per row
#pragma unroll
        for (int i = t; i < 128 * CPR; i += 256) {
            int m = i / CPR, j = i % CPR;
            cp16(uA + m * (KDIM * 2) + ((j * 16) ^ ((m & 7) << 4)),
                 Ab + (size_t)m * (KDIM * 2) + j * 16);
        }
    }
    // ---- B chunk loader ----
    auto loadB = [&](int buf, int kc0) {
        uint32_t dst = uB + buf * BSZ;
#pragma unroll
        for (int i = t; i < KC * 16; i += 256) {
            int k = i >> 4, j = i & 15;
            cp16(dst + k * BROW + ((j * 16) ^ ((k & 7) << 4)),
                 Bb + ((size_t)(kc0 + k) * HWPX + p0) * 2 + j * 16);
        }
    };
    loadB(0, 0);
    cp_commit();                 // group0: A + B0
    if (NCHUNK > 1) { loadB(1, KC); cp_commit(); }

    float acc[4][4][4];
#pragma unroll
    for (int mi = 0; mi < 4; mi++)
#pragma unroll
        for (int ni = 0; ni < 4; ni++)
#pragma unroll
            for (int r = 0; r < 4; r++) acc[mi][ni][r] = 0.f;

    // precomputed lane addresses
    const int a_m  = wm + (lane & 15);
    const int a_kb = (lane >> 4) * 16;                 // byte offset for k-half
    const uint32_t aBase = uA + a_m * (KDIM * 2);
    const uint32_t aSwz  = (a_m & 7) << 4;
    const int b_k  = lane & 15;
    const int b_nb = wp * 2 + (lane >> 4) * 16;        // byte offset of n within row
    const uint32_t bSwzK = (b_k & 7) << 4;

    for (int c = 0; c < NCHUNK; c++) {
        // on the final chunk the only outstanding group holds this chunk's
        // data — drain fully there (race fix, R4, protected).
        if (c == NCHUNK - 1) cp_wait<0>(); else cp_wait<1>();
        __syncthreads();
        const uint32_t bb = uB + (c & 1) * BSZ + b_k * BROW;
#pragma unroll
        for (int ks = 0; ks < KC / 16; ks++) {
            const int kB = ks * 32;                    // byte offset of k within A row chunk
            uint32_t a[4][4];
#pragma unroll
            for (int mi = 0; mi < 4; mi++)
                ldsm_x4(a[mi], aBase + mi * 16 * (KDIM * 2) +
                               (((c * KC * 2) + kB + a_kb) ^ aSwz));
            uint32_t bf[2][4];
#pragma unroll
            for (int h = 0; h < 2; h++)
                ldsm_x4_t(bf[h], bb + ks * 16 * BROW + ((b_nb + h * 32) ^ bSwzK));
#pragma unroll
            for (int mi = 0; mi < 4; mi++)
#pragma unroll
                for (int ni = 0; ni < 4; ni++)
                    mma16816(acc[mi][ni], a[mi], &bf[ni >> 1][(ni & 1) * 2]);
        }
        __syncthreads();
        if (c + 2 < NCHUNK) { loadB(c & 1, (c + 2) * KC); cp_commit(); }
    }

    // ---- epilogue ----
    const int erow = lane >> 2;
    const int ecol = (lane & 3) * 2;
    if (EP == 2) {
#pragma unroll
        for (int mi = 0; mi < 4; mi++) {
#pragma unroll
            for (int h = 0; h < 2; h++) {
                const int m = wm + mi * 16 + h * 8 + erow;
                const float bv = bias[m0 + m];
                const size_t rb = ((size_t)(b * OCH + m0 + m)) * HWPX + p0;
#pragma unroll
                for (int ni = 0; ni < 4; ni++) {
                    const size_t o = rb + wp + ni * 8 + ecol;
                    float2 xr = *(const float2*)&xres[o];
                    float2 v;
                    v.x = acc[mi][ni][2 * h]     + bv + xr.x;
                    v.y = acc[mi][ni][2 * h + 1] + bv + xr.y;
                    *(float2*)&out[o] = v;
                }
            }
        }
    } else {
        float rs[4][2];
#pragma unroll
        for (int mi = 0; mi < 4; mi++) {
#pragma unroll
            for (int h = 0; h < 2; h++) {
                const int m = wm + mi * 16 + h * 8 + erow;
                const float bv = bias[m0 + m];
                float s2 = 0.f;
#pragma unroll
                for (int ni = 0; ni < 4; ni++) {
                    float v0 = fmaxf(acc[mi][ni][2 * h]     + bv, 0.f);
                    float v1 = fmaxf(acc[mi][ni][2 * h + 1] + bv, 0.f);
                    s2 += v0 + v1;
                    if (MT == 0) {
                        size_t o = ((size_t)(b * KSEL + m)) * HWPX + p0 + wp + ni * 8 + ecol;
                        *(__nv_bfloat162*)&g_selb[o] = __floats2bfloat162_rn(v0, v1);
                    }
                }
                rs[mi][h] = s2;
            }
        }
        // reduce over the 4 lanes sharing a row (lane%4)
#pragma unroll
        for (int mi = 0; mi < 4; mi++)
#pragma unroll
            for (int h = 0; h < 2; h++) {
                rs[mi][h] += __shfl_xor_sync(0xffffffffu, rs[mi][h], 1);
                rs[mi][h] += __shfl_xor_sync(0xffffffffu, rs[mi][h], 2);
            }
        if ((lane & 3) == 0) {
#pragma unroll
            for (int mi = 0; mi < 4; mi++)
#pragma unroll
                for (int h = 0; h < 2; h++)
                    sg[(wid & 3) * 128 + wm + mi * 16 + h * 8 + erow] = rs[mi][h];
        }
        __syncthreads();
        if (t < 128)
            g_gap2_part[(b * MCH + m0 + t) * 128 + pc] =
                sg[t] + sg[128 + t] + sg[256 + t] + sg[384 + t];
    }
}

// =====================================================================
// k2: warp-cooperative scalar path (R5 rewrite).
// All dot products lane-strided (coalesced) + xor-tree reduce (deterministic).
// grid 8 (batch), 256 threads = 8 warps.
// =====================================================================
__global__ __launch_bounds__(256) void k2_scalar(const float* __restrict__ pw1_w,
                                                 const float* __restrict__ pw1_b,
                                                 const float* __restrict__ fc1_w,
                                                 const float* __restrict__ fc1_b,
                                                 const float* __restrict__ fc2_w,
                                                 const float* __restrict__ fc2_b,
                                                 const float* __restrict__ off_w,
                                                 const float* __restrict__ off_b,
                                                 const float* __restrict__ dw3,
                                                 const float* __restrict__ dw5,
                                                 const float* __restrict__ dw7)
{
    __shared__ float sgap[MCH], sgap2[MCH], shid[512], sscore[MCH];
    __shared__ float smask[KSEL], sscale[3], sshift[3];

    const int b = blockIdx.x;
    const int t = threadIdx.x;
    const int wid = t >> 5, lane = t & 31;

    // xmean into registers via smem
    __shared__ float sxm[CIN];
    if (t < CIN) sxm[t] = gXmean[b * CIN + t];
    __syncthreads();

    // gap[m] = dot(xmean, pw1_w[m,:]) + b  — warp per row, coalesced
    for (int m = wid; m < MCH; m += 8) {
        const float* wr = pw1_w + m * CIN;
        float a = 0.f;
#pragma unroll
        for (int c = lane; c < CIN; c += 32) a = fmaf(sxm[c], wr[c], a);
        a = wred(a);
        if (lane == 0) sgap[m] = a + pw1_b[m];
    }
    // gap2[m]: reduce 128 partials — warp per row, float4 per lane
    for (int m = wid; m < MCH; m += 8) {
        const float4* p4 = (const float4*)(g_gap2_part + (b * MCH + m) * 128);
        float4 v = p4[lane];
        float a = wred(v.x + v.y + v.z + v.w);
        if (lane == 0) sgap2[m] = a * (1.f / (float)HWPX);
    }
    __syncthreads();

    // fc1: 512 outputs of 256-dot — warp per output
    for (int j = wid; j < 512; j += 8) {
        const float* wr = fc1_w + j * MCH;
        float a = 0.f;
#pragma unroll
        for (int c = lane; c < MCH; c += 32) a = fmaf(sgap[c], wr[c], a);
        a = wred(a);
        if (lane == 0) shid[j] = fmaxf(a + fc1_b[j], 0.f);
    }
    __syncthreads();

    // fc2: 256 outputs of 512-dot — warp per output
    for (int j = wid; j < MCH; j += 8) {
        const float* wr = fc2_w + j * 512;
        float a = 0.f;
#pragma unroll
        for (int c = lane; c < 512; c += 32) a = fmaf(shid[c], wr[c], a);
        a = wred(a);
        if (lane == 0) sscore[j] = 1.f / (1.f + expf(-a));
    }
    // offsets: warps 0..5 (one per output r), overlap with fc2 tail via separate sync
    __syncthreads();

    if (wid < 6) {
        const int r = wid;
        const float* wr = off_w + r * MCH;
        float a = 0.f;
#pragma unroll
        for (int c = lane; c < MCH; c += 32) a = fmaf(sgap2[c], wr[c], a);
        a = wred(a);
        if (lane == 0) {
            float o = tanhf(a + off_b[r]);
            if ((r & 1) == 0) sscale[r >> 1] = 1.f / (1.f + expf(-o));
            else              sshift[r >> 1] = tanhf(o);
        }
    }
    if (t < KSEL) {
        float sc = sscore[t];
        int cnt = 0;
        for (int j = 0; j < MCH; j++) {
            float sj = sscore[j];
            cnt += (sj > sc) || (sj == sc && j < t);
        }
        smask[t] = (cnt < KSEL) ? 1.f : 0.f;
    }
    __syncthreads();

    for (int i = t; i < KSEL * 9; i += 256) {
        int c = i / 9, j = i % 9;
        g_w3[(b * KSEL + c) * 9 + j] = fmaf(dw3[c * 9 + j], 1.f + sscale[0], sshift[0]) * smask[c];
    }
    for (int i = t; i < KSEL * 25; i += 256) {
        int c = i / 25, j = i % 25;
        g_w5[(b * KSEL + c) * 25 + j] = fmaf(dw5[c * 25 + j], 1.f + sscale[1], sshift[1]) * smask[c];
    }
    for (int i = t; i < KSEL * 49; i += 256) {
        int c = i / 49, j = i % 49;
        g_w7[(b * KSEL + c) * 49 + j] = fmaf(dw7[c * 49 + j], 1.f + sscale[2], sshift[2]) * smask[c];
    }
}

// =====================================================================
// k3: fused depthwise 3x3+5x5+7x7, bf16 in/out, fp32 compute
// =====================================================================
__global__ __launch_bounds__(256) void k3_dwconv()
{
    __shared__ float s[38][38];
    __shared__ float sw[84];

    const int b = blockIdx.z;
    const int c = blockIdx.y;
    const int tile = blockIdx.x;
    const int ty0 = (tile >> 2) * 32;
    const int tx0 = (tile & 3) * 32;
    const int t = threadIdx.x;

    const __nv_bfloat16* in = g_selb + ((size_t)(b * KSEL + c)) * HWPX;

    for (int i = t; i < 38 * 38; i += 256) {
        int r = i / 38, cc = i % 38;
        int gy = ty0 + r - 3, gx = tx0 + cc - 3;
        s[r][cc] = (gy >= 0 && gy < HH && gx >= 0 && gx < WW) ? __bfloat162float(in[gy * WW + gx]) : 0.f;
    }
    if (t < 9)        sw[t] = g_w3[(b * KSEL + c) * 9 + t];
    else if (t < 34)  sw[t] = g_w5[(b * KSEL + c) * 25 + (t - 9)];
    else if (t < 83)  sw[t] = g_w7[(b * KSEL + c) * 49 + (t - 34)];
    __syncthreads();

    for (int i = t; i < 1024; i += 256) {
        int py = i >> 5, px = i & 31;
        float a3 = 0.f, a5 = 0.f, a7 = 0.f;
#pragma unroll
        for (int dy = -3; dy <= 3; dy++) {
#pragma unroll
            for (int dx = -3; dx <= 3; dx++) {
                float v = s[py + 3 + dy][px + 3 + dx];
                a7 = fmaf(sw[34 + (dy + 3) * 7 + (dx + 3)], v, a7);
                if (dy >= -2 && dy <= 2 && dx >= -2 && dx <= 2)
                    a5 = fmaf(sw[9 + (dy + 2) * 5 + (dx + 2)], v, a5);
                if (dy >= -1 && dy <= 1 && dx >= -1 && dx <= 1)
                    a3 = fmaf(sw[(dy + 1) * 3 + (dx + 1)], v, a3);
            }
        }
        size_t o = ((size_t)(b * (3 * KSEL) + c)) * HWPX + (ty0 + py) * WW + tx0 + px;
        g_fusedb[o]                           = __float2bfloat16(a3);
        g_fusedb[o + (size_t)KSEL * HWPX]     = __float2bfloat16(a5);
        g_fusedb[o + (size_t)2 * KSEL * HWPX] = __float2bfloat16(a7);
    }
}

// =====================================================================
extern "C" void kernel_launch(void* const* d_in, const int* in_sizes, int n_in,
                              void* d_out, int out_size)
{
    const float* x     = (const float*)d_in[0];
    const float* pw1_w = (const float*)d_in[1];
    const float* pw1_b = (const float*)d_in[2];
    const float* fc1_w = (const float*)d_in[3];
    const float* fc1_b = (const float*)d_in[4];
    const float* fc2_w = (const float*)d_in[5];
    const float* fc2_b = (const float*)d_in[6];
    const float* off_w = (const float*)d_in[7];
    const float* off_b = (const float*)d_in[8];
    const float* dw3   = (const float*)d_in[9];
    const float* dw5   = (const float*)d_in[10];
    const float* dw7   = (const float*)d_in[11];
    const float* pw_w  = (const float*)d_in[12];
    const float* pw_b  = (const float*)d_in[13];
    float* out = (float*)d_out;

    const int smem1 = 128 * 256 * 2 + 2 * 64 * 256 + 4 * 128 * 4 + 256;   // ~100KB
    const int smem2 = 128 * 384 * 2 + 2 * 64 * 256 + 4 * 128 * 4 + 256;   // ~132KB
    cudaFuncSetAttribute((const void*)kgemm<256, 1>, cudaFuncAttributeMaxDynamicSharedMemorySize, smem1);
    cudaFuncSetAttribute((const void*)kgemm<384, 2>, cudaFuncAttributeMaxDynamicSharedMemorySize, smem2);

    __nv_bfloat16 *gA1p, *gA2p, *gXbp, *gFbp;
    cudaGetSymbolAddress((void**)&gA1p, gA1);
    cudaGetSymbolAddress((void**)&gA2p, gA2);
    cudaGetSymbolAddress((void**)&gXbp, gXb);
    cudaGetSymbolAddress((void**)&gFbp, g_fusedb);

    kxc<<<BATCH * CIN, 256>>>(x);
    kprep<<<640, 256>>>(pw1_w, pw_w);
    kgemm<256, 1><<<dim3(128, 2, BATCH), 256, smem1>>>(gA1p, gXbp, pw1_b, nullptr, nullptr);
    k2_scalar<<<BATCH, 256>>>(pw1_w, pw1_b, fc1_w, fc1_b, fc2_w, fc2_b, off_w, off_b, dw3, dw5, dw7);
    k3_dwconv<<<dim3(16, KSEL, BATCH), 256>>>();
    kgemm<384, 2><<<dim3(128, 2, BATCH), 256, smem2>>>(gA2p, gFbp, pw_b, x, out);
}

// round 6
// speedup vs baseline: 2.7306x; 1.0062x over previous
#include <cuda_runtime.h>
#include <cuda_bf16.h>
#include <cstdint>
#include <math.h>

#define BATCH 8
#define CIN   256
#define MCH   256
#define OCH   256
#define HH    128
#define WW    128
#define HWPX  16384
#define KSEL  128

// ---------------- device scratch ----------------
__device__ __align__(128) __nv_bfloat16 gXb[(size_t)BATCH * CIN * HWPX];           // x bf16
__device__ __align__(128) __nv_bfloat16 g_selb[(size_t)BATCH * KSEL * HWPX];       // relu(h)[:,:128] bf16
__device__ __align__(128) __nv_bfloat16 g_fusedb[(size_t)BATCH * 3 * KSEL * HWPX]; // dwconv out bf16
__device__ __align__(128) __nv_bfloat16 gA1[2 * 128 * 256];                        // pw1_w bf16 linear
__device__ __align__(128) __nv_bfloat16 gA2[2 * 128 * 384];                        // pw_w[:, :384] bf16 linear
__device__ float gXmean[BATCH * CIN];
__device__ float g_gap2_part[BATCH * MCH * 128];
__device__ float g_w3[BATCH * KSEL * 9];
__device__ float g_w5[BATCH * KSEL * 25];
__device__ float g_w7[BATCH * KSEL * 49];

// ---------------- PTX helpers (baseline compute_103 features only) ----------------
__device__ __forceinline__ uint32_t smem_u32(const void* p) {
    uint32_t a;
    asm("{ .reg .u64 t; cvta.to.shared.u64 t, %1; cvt.u32.u64 %0, t; }" : "=r"(a) : "l"(p));
    return a;
}
__device__ __forceinline__ void cp16(uint32_t dst, const void* src) {
    asm volatile("cp.async.cg.shared.global [%0], [%1], 16;" :: "r"(dst), "l"(src) : "memory");
}
__device__ __forceinline__ void cp_commit() { asm volatile("cp.async.commit_group;" ::: "memory"); }
template<int N> __device__ __forceinline__ void cp_wait() { asm volatile("cp.async.wait_group %0;" :: "n"(N) : "memory"); }

__device__ __forceinline__ void ldsm_x4(uint32_t* r, uint32_t addr) {
    asm volatile("ldmatrix.sync.aligned.m8n8.x4.shared.b16 {%0,%1,%2,%3}, [%4];"
                 : "=r"(r[0]), "=r"(r[1]), "=r"(r[2]), "=r"(r[3]) : "r"(addr));
}
__device__ __forceinline__ void ldsm_x4_t(uint32_t* r, uint32_t addr) {
    asm volatile("ldmatrix.sync.aligned.m8n8.x4.trans.shared.b16 {%0,%1,%2,%3}, [%4];"
                 : "=r"(r[0]), "=r"(r[1]), "=r"(r[2]), "=r"(r[3]) : "r"(addr));
}
__device__ __forceinline__ void mma16816(float* d, const uint32_t* a, const uint32_t* b) {
    asm volatile("mma.sync.aligned.m16n8k16.row.col.f32.bf16.bf16.f32 "
                 "{%0,%1,%2,%3}, {%4,%5,%6,%7}, {%8,%9}, {%0,%1,%2,%3};"
                 : "+f"(d[0]), "+f"(d[1]), "+f"(d[2]), "+f"(d[3])
                 : "r"(a[0]), "r"(a[1]), "r"(a[2]), "r"(a[3]), "r"(b[0]), "r"(b[1]));
}
__device__ __forceinline__ float wred(float v) {
    v += __shfl_xor_sync(0xffffffffu, v, 16);
    v += __shfl_xor_sync(0xffffffffu, v, 8);
    v += __shfl_xor_sync(0xffffffffu, v, 4);
    v += __shfl_xor_sync(0xffffffffu, v, 2);
    v += __shfl_xor_sync(0xffffffffu, v, 1);
    return v;
}

// =====================================================================
// kxc: x fp32 -> bf16 + exact fp32 row means (score path stays exact)
// =====================================================================
__global__ __launch_bounds__(256) void kxc(const float* __restrict__ x)
{
    __shared__ float red[256];
    const int row = blockIdx.x;
    const int t = threadIdx.x;
    const float4* in4 = (const float4*)(x + (size_t)row * HWPX);
    __nv_bfloat162* ob = (__nv_bfloat162*)(gXb + (size_t)row * HWPX);
    float s = 0.f;
#pragma unroll
    for (int it = 0; it < 16; it++) {
        int j = t + it * 256;
        float4 v = in4[j];
        s += v.x + v.y + v.z + v.w;
        ob[j * 2 + 0] = __floats2bfloat162_rn(v.x, v.y);
        ob[j * 2 + 1] = __floats2bfloat162_rn(v.z, v.w);
    }
    red[t] = s;
    __syncthreads();
    for (int o = 128; o > 0; o >>= 1) {
        if (t < o) red[t] += red[t + o];
        __syncthreads();
    }
    if (t == 0) gXmean[row] = red[0] * (1.f / (float)HWPX);
}

// =====================================================================
// kprep: weights -> bf16 linear row-major images
// =====================================================================
__global__ __launch_bounds__(256) void kprep(const float* __restrict__ pw1_w,
                                             const float* __restrict__ pw_w)
{
    int i = blockIdx.x * 256 + threadIdx.x;
    if (i < 65536) {
        gA1[i] = __float2bfloat16(pw1_w[i]);
    } else {
        int j = i - 65536;            // 256 rows x 384 cols
        int m = j / 384, k = j % 384;
        gA2[j] = __float2bfloat16(pw_w[m * 768 + k]);
    }
}

// =====================================================================
// kgemm<KDIM, EP>: mma.sync bf16 GEMM. CTA 128m x 128p, 8 warps (2x4),
// warp tile 64m x 32p. A full-K in smem, B double-buffered KC=64 chunks.
// EP=1: +bias, relu, bf16 sel store (MT==0), deterministic gap2 partials.
// EP=2: +bias +residual, fp32 out.
// grid (128, 2, BATCH), 256 threads.
// =====================================================================
template<int KDIM, int EP>
__global__ __launch_bounds__(256, 1)
void kgemm(const __nv_bfloat16* __restrict__ Aimg,
           const __nv_bfloat16* __restrict__ Bsrc,
           const float* __restrict__ bias,
           const float* __restrict__ xres,
           float* __restrict__ out)
{
    constexpr int KC = 64;
    constexpr int NCHUNK = KDIM / KC;
    constexpr int ASZ = 128 * KDIM * 2;      // bytes
    constexpr int BROW = 256;                // bytes per B k-row (128 bf16)
    constexpr int BSZ = KC * BROW;           // 16KB per buffer

    extern __shared__ char sraw[];
    const uint32_t rawu = smem_u32(sraw);
    const uint32_t sbase = (rawu + 127u) & ~127u;
    const uint32_t uA = sbase;
    const uint32_t uB = sbase + ASZ;
    float* sg = (float*)(sraw + (sbase - rawu) + ASZ + 2 * BSZ);   // [4][128] (EP1)

    const int t = threadIdx.x, wid = t >> 5, lane = t & 31;
    const int b = blockIdx.z, MT = blockIdx.y, pc = blockIdx.x;
    const int m0 = MT * 128;
    const int p0 = pc * 128;
    const int wm = (wid >> 2) * 64;          // warp m offset in tile
    const int wp = (wid & 3) * 32;           // warp p offset in tile

    const char* Bb = (const char*)(Bsrc + (size_t)b * KDIM * HWPX);
    const char* Ab = (const char*)(Aimg + (size_t)MT * 128 * KDIM);

    // ---- A load (swizzled), full K ----
    {
        constexpr int CPR = KDIM / 8;        // 16B chunks per row
#pragma unroll
        for (int i = t; i < 128 * CPR; i += 256) {
            int m = i / CPR, j = i % CPR;
            cp16(uA + m * (KDIM * 2) + ((j * 16) ^ ((m & 7) << 4)),
                 Ab + (size_t)m * (KDIM * 2) + j * 16);
        }
    }
    // ---- B chunk loader ----
    auto loadB = [&](int buf, int kc0) {
        uint32_t dst = uB + buf * BSZ;
#pragma unroll
        for (int i = t; i < KC * 16; i += 256) {
            int k = i >> 4, j = i & 15;
            cp16(dst + k * BROW + ((j * 16) ^ ((k & 7) << 4)),
                 Bb + ((size_t)(kc0 + k) * HWPX + p0) * 2 + j * 16);
        }
    };
    loadB(0, 0);
    cp_commit();                 // group0: A + B0
    if (NCHUNK > 1) { loadB(1, KC); cp_commit(); }

    float acc[4][4][4];
#pragma unroll
    for (int mi = 0; mi < 4; mi++)
#pragma unroll
        for (int ni = 0; ni < 4; ni++)
#pragma unroll
            for (int r = 0; r < 4; r++) acc[mi][ni][r] = 0.f;

    // precomputed lane addresses
    const int a_m  = wm + (lane & 15);
    const int a_kb = (lane >> 4) * 16;                 // byte offset for k-half
    const uint32_t aBase = uA + a_m * (KDIM * 2);
    const uint32_t aSwz  = (a_m & 7) << 4;
    const int b_k  = lane & 15;
    const int b_nb = wp * 2 + (lane >> 4) * 16;        // byte offset of n within row
    const uint32_t bSwzK = (b_k & 7) << 4;

    for (int c = 0; c < NCHUNK; c++) {
        // on the final chunk the only outstanding group holds this chunk's
        // data — drain fully there (race fix, R4, protected).
        if (c == NCHUNK - 1) cp_wait<0>(); else cp_wait<1>();
        __syncthreads();
        const uint32_t bb = uB + (c & 1) * BSZ + b_k * BROW;
#pragma unroll
        for (int ks = 0; ks < KC / 16; ks++) {
            const int kB = ks * 32;                    // byte offset of k within A row chunk
            uint32_t a[4][4];
#pragma unroll
            for (int mi = 0; mi < 4; mi++)
                ldsm_x4(a[mi], aBase + mi * 16 * (KDIM * 2) +
                               (((c * KC * 2) + kB + a_kb) ^ aSwz));
            uint32_t bf[2][4];
#pragma unroll
            for (int h = 0; h < 2; h++)
                ldsm_x4_t(bf[h], bb + ks * 16 * BROW + ((b_nb + h * 32) ^ bSwzK));
#pragma unroll
            for (int mi = 0; mi < 4; mi++)
#pragma unroll
                for (int ni = 0; ni < 4; ni++)
                    mma16816(acc[mi][ni], a[mi], &bf[ni >> 1][(ni & 1) * 2]);
        }
        __syncthreads();
        if (c + 2 < NCHUNK) { loadB(c & 1, (c + 2) * KC); cp_commit(); }
    }

    // ---- epilogue ----
    const int erow = lane >> 2;
    const int ecol = (lane & 3) * 2;
    if (EP == 2) {
#pragma unroll
        for (int mi = 0; mi < 4; mi++) {
#pragma unroll
            for (int h = 0; h < 2; h++) {
                const int m = wm + mi * 16 + h * 8 + erow;
                const float bv = bias[m0 + m];
                const size_t rb = ((size_t)(b * OCH + m0 + m)) * HWPX + p0;
#pragma unroll
                for (int ni = 0; ni < 4; ni++) {
                    const size_t o = rb + wp + ni * 8 + ecol;
                    float2 xr = *(const float2*)&xres[o];
                    float2 v;
                    v.x = acc[mi][ni][2 * h]     + bv + xr.x;
                    v.y = acc[mi][ni][2 * h + 1] + bv + xr.y;
                    *(float2*)&out[o] = v;
                }
            }
        }
    } else {
        float rs[4][2];
#pragma unroll
        for (int mi = 0; mi < 4; mi++) {
#pragma unroll
            for (int h = 0; h < 2; h++) {
                const int m = wm + mi * 16 + h * 8 + erow;
                const float bv = bias[m0 + m];
                float s2 = 0.f;
#pragma unroll
                for (int ni = 0; ni < 4; ni++) {
                    float v0 = fmaxf(acc[mi][ni][2 * h]     + bv, 0.f);
                    float v1 = fmaxf(acc[mi][ni][2 * h + 1] + bv, 0.f);
                    s2 += v0 + v1;
                    if (MT == 0) {
                        size_t o = ((size_t)(b * KSEL + m)) * HWPX + p0 + wp + ni * 8 + ecol;
                        *(__nv_bfloat162*)&g_selb[o] = __floats2bfloat162_rn(v0, v1);
                    }
                }
                rs[mi][h] = s2;
            }
        }
        // reduce over the 4 lanes sharing a row (lane%4)
#pragma unroll
        for (int mi = 0; mi < 4; mi++)
#pragma unroll
            for (int h = 0; h < 2; h++) {
                rs[mi][h] += __shfl_xor_sync(0xffffffffu, rs[mi][h], 1);
                rs[mi][h] += __shfl_xor_sync(0xffffffffu, rs[mi][h], 2);
            }
        if ((lane & 3) == 0) {
#pragma unroll
            for (int mi = 0; mi < 4; mi++)
#pragma unroll
                for (int h = 0; h < 2; h++)
                    sg[(wid & 3) * 128 + wm + mi * 16 + h * 8 + erow] = rs[mi][h];
        }
        __syncthreads();
        if (t < 128)
            g_gap2_part[(b * MCH + m0 + t) * 128 + pc] =
                sg[t] + sg[128 + t] + sg[256 + t] + sg[384 + t];
    }
}

// =====================================================================
// k2_all (R6): ONE block, 1024 threads, all 8 batches together.
// Warp-per-output-row over all batches: weights read once, 8x reuse,
// iteration counts cut 4-8x vs R5. Per-(batch,output) summation order
// identical to R5 (lane-strided + xor tree) -> scores bit-identical.
// =====================================================================
__global__ __launch_bounds__(1024) void k2_all(const float* __restrict__ pw1_w,
                                               const float* __restrict__ pw1_b,
                                               const float* __restrict__ fc1_w,
                                               const float* __restrict__ fc1_b,
                                               const float* __restrict__ fc2_w,
                                               const float* __restrict__ fc2_b,
                                               const float* __restrict__ off_w,
                                               const float* __restrict__ off_b,
                                               const float* __restrict__ dw3,
                                               const float* __restrict__ dw5,
                                               const float* __restrict__ dw7)
{
    extern __shared__ float sm[];
    float* sxm    = sm;             // [8*256]
    float* sgap   = sxm + 2048;     // [8*256]
    float* sgap2  = sgap + 2048;    // [8*256]
    float* shid   = sgap2 + 2048;   // [8*512]
    float* sscore = shid + 4096;    // [8*256]
    float* smask  = sscore + 2048;  // [8*128]
    float* sscl   = smask + 1024;   // [8*3]
    float* ssht   = sscl + 24;      // [8*3]

    const int t = threadIdx.x, wid = t >> 5, lane = t & 31;

    for (int i = t; i < 2048; i += 1024) sxm[i] = gXmean[i];
    __syncthreads();

    // gap[b][m]: warp per m, 8 batches at once
    for (int m = wid; m < MCH; m += 32) {
        const float* wr = pw1_w + m * CIN;
        float acc[8] = {0.f, 0.f, 0.f, 0.f, 0.f, 0.f, 0.f, 0.f};
        for (int c = lane; c < CIN; c += 32) {
            float w = wr[c];
#pragma unroll
            for (int bb = 0; bb < 8; bb++) acc[bb] = fmaf(sxm[bb * 256 + c], w, acc[bb]);
        }
#pragma unroll
        for (int bb = 0; bb < 8; bb++) acc[bb] = wred(acc[bb]);
        if (lane == 0) {
            float bv = pw1_b[m];
#pragma unroll
            for (int bb = 0; bb < 8; bb++) sgap[bb * 256 + m] = acc[bb] + bv;
        }
    }
    // gap2: warp per (b,m) row of 128 partials (coalesced float4 + wred)
    for (int rr = wid; rr < 2048; rr += 32) {
        const float4* p4 = (const float4*)(g_gap2_part + rr * 128);
        float4 v = p4[lane];
        float a = wred(v.x + v.y + v.z + v.w);
        if (lane == 0) sgap2[rr] = a * (1.f / (float)HWPX);
    }
    __syncthreads();

    // fc1: warp per j (512), 8 batches
    for (int j = wid; j < 512; j += 32) {
        const float* wr = fc1_w + j * MCH;
        float acc[8] = {0.f, 0.f, 0.f, 0.f, 0.f, 0.f, 0.f, 0.f};
        for (int c = lane; c < MCH; c += 32) {
            float w = wr[c];
#pragma unroll
            for (int bb = 0; bb < 8; bb++) acc[bb] = fmaf(sgap[bb * 256 + c], w, acc[bb]);
        }
#pragma unroll
        for (int bb = 0; bb < 8; bb++) acc[bb] = wred(acc[bb]);
        if (lane == 0) {
            float bv = fc1_b[j];
#pragma unroll
            for (int bb = 0; bb < 8; bb++) shid[bb * 512 + j] = fmaxf(acc[bb] + bv, 0.f);
        }
    }
    __syncthreads();

    // fc2: warp per j (256), 8 batches
    for (int j = wid; j < MCH; j += 32) {
        const float* wr = fc2_w + j * 512;
        float acc[8] = {0.f, 0.f, 0.f, 0.f, 0.f, 0.f, 0.f, 0.f};
        for (int c = lane; c < 512; c += 32) {
            float w = wr[c];
#pragma unroll
            for (int bb = 0; bb < 8; bb++) acc[bb] = fmaf(shid[bb * 512 + c], w, acc[bb]);
        }
#pragma unroll
        for (int bb = 0; bb < 8; bb++) acc[bb] = wred(acc[bb]);
        if (lane == 0) {
            float bv = fc2_b[j];
#pragma unroll
            for (int bb = 0; bb < 8; bb++)
                sscore[bb * 256 + j] = 1.f / (1.f + expf(-(acc[bb] + bv)));
        }
    }
    // offsets: 48 warp-dots (b,r), uses sgap2 (synced above)
    for (int task = wid; task < 48; task += 32) {
        int bb = task / 6, r = task % 6;
        const float* wr = off_w + r * MCH;
        float a = 0.f;
        for (int c = lane; c < MCH; c += 32) a = fmaf(sgap2[bb * 256 + c], wr[c], a);
        a = wred(a);
        if (lane == 0) {
            float o = tanhf(a + off_b[r]);
            if ((r & 1) == 0) sscl[bb * 3 + (r >> 1)] = 1.f / (1.f + expf(-o));
            else              ssht[bb * 3 + (r >> 1)] = tanhf(o);
        }
    }
    __syncthreads();

    // top-k mask: thread = (b, tt)
    {
        int bb = t >> 7, tt = t & 127;
        const float* sc_ = sscore + bb * 256;
        float sc = sc_[tt];
        int cnt = 0;
        for (int j = 0; j < MCH; j++) {
            float sj = sc_[j];
            cnt += (sj > sc) || (sj == sc && j < tt);
        }
        smask[bb * 128 + tt] = (cnt < KSEL) ? 1.f : 0.f;
    }
    __syncthreads();

    // effective depthwise weights (mask folded in)
    for (int i = t; i < 8 * 128 * 9; i += 1024) {
        int bb = i / 1152, rem = i % 1152, c = rem / 9;
        g_w3[i] = fmaf(dw3[rem], 1.f + sscl[bb * 3 + 0], ssht[bb * 3 + 0]) * smask[bb * 128 + c];
    }
    for (int i = t; i < 8 * 128 * 25; i += 1024) {
        int bb = i / 3200, rem = i % 3200, c = rem / 25;
        g_w5[i] = fmaf(dw5[rem], 1.f + sscl[bb * 3 + 1], ssht[bb * 3 + 1]) * smask[bb * 128 + c];
    }
    for (int i = t; i < 8 * 128 * 49; i += 1024) {
        int bb = i / 6272, rem = i % 6272, c = rem / 49;
        g_w7[i] = fmaf(dw7[rem], 1.f + sscl[bb * 3 + 2], ssht[bb * 3 + 2]) * smask[bb * 128 + c];
    }
}

// =====================================================================
// k3: fused depthwise 3x3+5x5+7x7, bf16 in/out, fp32 compute
// =====================================================================
__global__ __launch_bounds__(256) void k3_dwconv()
{
    __shared__ float s[38][38];
    __shared__ float sw[84];

    const int b = blockIdx.z;
    const int c = blockIdx.y;
    const int tile = blockIdx.x;
    const int ty0 = (tile >> 2) * 32;
    const int tx0 = (tile & 3) * 32;
    const int t = threadIdx.x;

    const __nv_bfloat16* in = g_selb + ((size_t)(b * KSEL + c)) * HWPX;

    for (int i = t; i < 38 * 38; i += 256) {
        int r = i / 38, cc = i % 38;
        int gy = ty0 + r - 3, gx = tx0 + cc - 3;
        s[r][cc] = (gy >= 0 && gy < HH && gx >= 0 && gx < WW) ? __bfloat162float(in[gy * WW + gx]) : 0.f;
    }
    if (t < 9)        sw[t] = g_w3[(b * KSEL + c) * 9 + t];
    else if (t < 34)  sw[t] = g_w5[(b * KSEL + c) * 25 + (t - 9)];
    else if (t < 83)  sw[t] = g_w7[(b * KSEL + c) * 49 + (t - 34)];
    __syncthreads();

    for (int i = t; i < 1024; i += 256) {
        int py = i >> 5, px = i & 31;
        float a3 = 0.f, a5 = 0.f, a7 = 0.f;
#pragma unroll
        for (int dy = -3; dy <= 3; dy++) {
#pragma unroll
            for (int dx = -3; dx <= 3; dx++) {
                float v = s[py + 3 + dy][px + 3 + dx];
                a7 = fmaf(sw[34 + (dy + 3) * 7 + (dx + 3)], v, a7);
                if (dy >= -2 && dy <= 2 && dx >= -2 && dx <= 2)
                    a5 = fmaf(sw[9 + (dy + 2) * 5 + (dx + 2)], v, a5);
                if (dy >= -1 && dy <= 1 && dx >= -1 && dx <= 1)
                    a3 = fmaf(sw[(dy + 1) * 3 + (dx + 1)], v, a3);
            }
        }
        size_t o = ((size_t)(b * (3 * KSEL) + c)) * HWPX + (ty0 + py) * WW + tx0 + px;
        g_fusedb[o]                           = __float2bfloat16(a3);
        g_fusedb[o + (size_t)KSEL * HWPX]     = __float2bfloat16(a5);
        g_fusedb[o + (size_t)2 * KSEL * HWPX] = __float2bfloat16(a7);
    }
}

// =====================================================================
extern "C" void kernel_launch(void* const* d_in, const int* in_sizes, int n_in,
                              void* d_out, int out_size)
{
    const float* x     = (const float*)d_in[0];
    const float* pw1_w = (const float*)d_in[1];
    const float* pw1_b = (const float*)d_in[2];
    const float* fc1_w = (const float*)d_in[3];
    const float* fc1_b = (const float*)d_in[4];
    const float* fc2_w = (const float*)d_in[5];
    const float* fc2_b = (const float*)d_in[6];
    const float* off_w = (const float*)d_in[7];
    const float* off_b = (const float*)d_in[8];
    const float* dw3   = (const float*)d_in[9];
    const float* dw5   = (const float*)d_in[10];
    const float* dw7   = (const float*)d_in[11];
    const float* pw_w  = (const float*)d_in[12];
    const float* pw_b  = (const float*)d_in[13];
    float* out = (float*)d_out;

    const int smem1 = 128 * 256 * 2 + 2 * 64 * 256 + 4 * 128 * 4 + 256;   // ~100KB
    const int smem2 = 128 * 384 * 2 + 2 * 64 * 256 + 4 * 128 * 4 + 256;   // ~132KB
    const int smemK2 = (2048 * 3 + 4096 + 2048 + 1024 + 48 + 32) * 4;     // ~54KB
    cudaFuncSetAttribute((const void*)kgemm<256, 1>, cudaFuncAttributeMaxDynamicSharedMemorySize, smem1);
    cudaFuncSetAttribute((const void*)kgemm<384, 2>, cudaFuncAttributeMaxDynamicSharedMemorySize, smem2);
    cudaFuncSetAttribute((const void*)k2_all, cudaFuncAttributeMaxDynamicSharedMemorySize, smemK2);

    __nv_bfloat16 *gA1p, *gA2p, *gXbp, *gFbp;
    cudaGetSymbolAddress((void**)&gA1p, gA1);
    cudaGetSymbolAddress((void**)&gA2p, gA2);
    cudaGetSymbolAddress((void**)&gXbp, gXb);
    cudaGetSymbolAddress((void**)&gFbp, g_fusedb);

    kxc<<<BATCH * CIN, 256>>>(x);
    kprep<<<640, 256>>>(pw1_w, pw_w);
    kgemm<256, 1><<<dim3(128, 2, BATCH), 256, smem1>>>(gA1p, gXbp, pw1_b, nullptr, nullptr);
    k2_all<<<1, 1024, smemK2>>>(pw1_w, pw1_b, fc1_w, fc1_b, fc2_w, fc2_b, off_w, off_b, dw3, dw5, dw7);
    k3_dwconv<<<dim3(16, KSEL, BATCH), 256>>>();
    kgemm<384, 2><<<dim3(128, 2, BATCH), 256, smem2>>>(gA2p, gFbp, pw_b, x, out);
}

// round 7
// speedup vs baseline: 3.3754x; 1.2361x over previous
#include <cuda_runtime.h>
#include <cuda_bf16.h>
#include <cstdint>
#include <math.h>

#define BATCH 8
#define CIN   256
#define MCH   256
#define OCH   256
#define HH    128
#define WW    128
#define HWPX  16384
#define KSEL  128

// ---------------- device scratch ----------------
__device__ __align__(128) __nv_bfloat16 gXb[(size_t)BATCH * CIN * HWPX];           // x bf16
__device__ __align__(128) __nv_bfloat16 g_selb[(size_t)BATCH * KSEL * HWPX];       // relu(h)[:,:128] bf16
__device__ __align__(128) __nv_bfloat16 g_fusedb[(size_t)BATCH * 3 * KSEL * HWPX]; // dwconv out bf16
__device__ __align__(128) __nv_bfloat16 gA1[256 * 256];                            // pw1_w bf16 linear
__device__ __align__(128) __nv_bfloat16 gA2[256 * 384];                            // pw_w[:, :384] bf16 linear
__device__ float gXmean[BATCH * CIN];
__device__ float g_gap2_part[BATCH * MCH * 128];
__device__ float g_gapv[BATCH * MCH];
__device__ float g_gap2v[BATCH * MCH];
__device__ float g_hidv[BATCH * 512];
__device__ float g_scorev[BATCH * MCH];
__device__ float g_w3[BATCH * KSEL * 9];
__device__ float g_w5[BATCH * KSEL * 25];
__device__ float g_w7[BATCH * KSEL * 49];

// ---------------- PTX helpers (baseline compute_103 features only) ----------------
__device__ __forceinline__ uint32_t smem_u32(const void* p) {
    uint32_t a;
    asm("{ .reg .u64 t; cvta.to.shared.u64 t, %1; cvt.u32.u64 %0, t; }" : "=r"(a) : "l"(p));
    return a;
}
__device__ __forceinline__ void cp16(uint32_t dst, const void* src) {
    asm volatile("cp.async.cg.shared.global [%0], [%1], 16;" :: "r"(dst), "l"(src) : "memory");
}
__device__ __forceinline__ void cp_commit() { asm volatile("cp.async.commit_group;" ::: "memory"); }
template<int N> __device__ __forceinline__ void cp_wait() { asm volatile("cp.async.wait_group %0;" :: "n"(N) : "memory"); }

__device__ __forceinline__ void ldsm_x4(uint32_t* r, uint32_t addr) {
    asm volatile("ldmatrix.sync.aligned.m8n8.x4.shared.b16 {%0,%1,%2,%3}, [%4];"
                 : "=r"(r[0]), "=r"(r[1]), "=r"(r[2]), "=r"(r[3]) : "r"(addr));
}
__device__ __forceinline__ void ldsm_x4_t(uint32_t* r, uint32_t addr) {
    asm volatile("ldmatrix.sync.aligned.m8n8.x4.trans.shared.b16 {%0,%1,%2,%3}, [%4];"
                 : "=r"(r[0]), "=r"(r[1]), "=r"(r[2]), "=r"(r[3]) : "r"(addr));
}
__device__ __forceinline__ void mma16816(float* d, const uint32_t* a, const uint32_t* b) {
    asm volatile("mma.sync.aligned.m16n8k16.row.col.f32.bf16.bf16.f32 "
                 "{%0,%1,%2,%3}, {%4,%5,%6,%7}, {%8,%9}, {%0,%1,%2,%3};"
                 : "+f"(d[0]), "+f"(d[1]), "+f"(d[2]), "+f"(d[3])
                 : "r"(a[0]), "r"(a[1]), "r"(a[2]), "r"(a[3]), "r"(b[0]), "r"(b[1]));
}
__device__ __forceinline__ float wred(float v) {
    v += __shfl_xor_sync(0xffffffffu, v, 16);
    v += __shfl_xor_sync(0xffffffffu, v, 8);
    v += __shfl_xor_sync(0xffffffffu, v, 4);
    v += __shfl_xor_sync(0xffffffffu, v, 2);
    v += __shfl_xor_sync(0xffffffffu, v, 1);
    return v;
}

// =====================================================================
// kxc: x fp32 -> bf16 + exact fp32 row means (score path stays exact)
// =====================================================================
__global__ __launch_bounds__(256) void kxc(const float* __restrict__ x)
{
    __shared__ float red[256];
    const int row = blockIdx.x;
    const int t = threadIdx.x;
    const float4* in4 = (const float4*)(x + (size_t)row * HWPX);
    __nv_bfloat162* ob = (__nv_bfloat162*)(gXb + (size_t)row * HWPX);
    float s = 0.f;
#pragma unroll
    for (int it = 0; it < 16; it++) {
        int j = t + it * 256;
        float4 v = in4[j];
        s += v.x + v.y + v.z + v.w;
        ob[j * 2 + 0] = __floats2bfloat162_rn(v.x, v.y);
        ob[j * 2 + 1] = __floats2bfloat162_rn(v.z, v.w);
    }
    red[t] = s;
    __syncthreads();
    for (int o = 128; o > 0; o >>= 1) {
        if (t < o) red[t] += red[t + o];
        __syncthreads();
    }
    if (t == 0) gXmean[row] = red[0] * (1.f / (float)HWPX);
}

// =====================================================================
// kprep: weights -> bf16 linear row-major images
// =====================================================================
__global__ __launch_bounds__(256) void kprep(const float* __restrict__ pw1_w,
                                             const float* __restrict__ pw_w)
{
    int i = blockIdx.x * 256 + threadIdx.x;
    if (i < 65536) {
        gA1[i] = __float2bfloat16(pw1_w[i]);
    } else {
        int j = i - 65536;            // 256 rows x 384 cols
        int m = j / 384, k = j % 384;
        gA2[j] = __float2bfloat16(pw_w[m * 768 + k]);
    }
}

// =====================================================================
// kgemm<KDIM, EP> (R7: M=256 merged): mma.sync bf16 GEMM.
// CTA 256m x 128p, 8 warps (2x4), warp tile 128m x 32p.
// A full-K in smem (read once), B double-buffered KC=64 chunks (read ONCE).
// EP=1: +bias, relu, bf16 sel store (m<128), deterministic gap2 partials.
// EP=2: +bias +residual, fp32 out.
// grid (128, 1, BATCH), 256 threads.
// =====================================================================
template<int KDIM, int EP>
__global__ __launch_bounds__(256, 1)
void kgemm(const __nv_bfloat16* __restrict__ Aimg,
           const __nv_bfloat16* __restrict__ Bsrc,
           const float* __restrict__ bias,
           const float* __restrict__ xres,
           float* __restrict__ out)
{
    constexpr int KC = 64;
    constexpr int NCHUNK = KDIM / KC;
    constexpr int ASZ = 256 * KDIM * 2;      // bytes (256 m-rows)
    constexpr int BROW = 256;                // bytes per B k-row (128 bf16)
    constexpr int BSZ = KC * BROW;           // 16KB per buffer

    extern __shared__ char sraw[];
    const uint32_t rawu = smem_u32(sraw);
    const uint32_t sbase = (rawu + 127u) & ~127u;
    const uint32_t uA = sbase;
    const uint32_t uB = sbase + ASZ;
    float* sg = (float*)(sraw + (sbase - rawu) + ASZ + 2 * BSZ);   // [4][256] (EP1)

    const int t = threadIdx.x, wid = t >> 5, lane = t & 31;
    const int b = blockIdx.z, pc = blockIdx.x;
    const int p0 = pc * 128;
    const int wm = (wid >> 2) * 128;         // warp m offset (0 or 128)
    const int wp = (wid & 3) * 32;           // warp p offset

    const char* Bb = (const char*)(Bsrc + (size_t)b * KDIM * HWPX);
    const char* Ab = (const char*)Aimg;

    // ---- A load (swizzled), full 256 x K ----
    {
        constexpr int CPR = KDIM / 8;        // 16B chunks per row
        for (int i = t; i < 256 * CPR; i += 256) {
            int m = i / CPR, j = i % CPR;
            cp16(uA + m * (KDIM * 2) + ((j * 16) ^ ((m & 7) << 4)),
                 Ab + (size_t)m * (KDIM * 2) + j * 16);
        }
    }
    // ---- B chunk loader ----
    auto loadB = [&](int buf, int kc0) {
        uint32_t dst = uB + buf * BSZ;
#pragma unroll
        for (int i = t; i < KC * 16; i += 256) {
            int k = i >> 4, j = i & 15;
            cp16(dst + k * BROW + ((j * 16) ^ ((k & 7) << 4)),
                 Bb + ((size_t)(kc0 + k) * HWPX + p0) * 2 + j * 16);
        }
    };
    loadB(0, 0);
    cp_commit();                 // group0: A + B0
    if (NCHUNK > 1) { loadB(1, KC); cp_commit(); }

    float acc[8][4][4];
#pragma unroll
    for (int mi = 0; mi < 8; mi++)
#pragma unroll
        for (int ni = 0; ni < 4; ni++)
#pragma unroll
            for (int r = 0; r < 4; r++) acc[mi][ni][r] = 0.f;

    // precomputed lane addresses
    const int a_m  = wm + (lane & 15);
    const int a_kb = (lane >> 4) * 16;                 // byte offset for k-half
    const uint32_t aBase = uA + a_m * (KDIM * 2);
    const uint32_t aSwz  = (a_m & 7) << 4;
    const int b_k  = lane & 15;
    const int b_nb = wp * 2 + (lane >> 4) * 16;        // byte offset of n within row
    const uint32_t bSwzK = (b_k & 7) << 4;

    for (int c = 0; c < NCHUNK; c++) {
        // on the final chunk the only outstanding group holds this chunk's
        // data — drain fully there (race fix, R4, protected).
        if (c == NCHUNK - 1) cp_wait<0>(); else cp_wait<1>();
        __syncthreads();
        const uint32_t bb = uB + (c & 1) * BSZ + b_k * BROW;
#pragma unroll
        for (int ks = 0; ks < KC / 16; ks++) {
            const int kB = ks * 32;                    // byte offset of k within chunk
            uint32_t bf[2][4];
#pragma unroll
            for (int h = 0; h < 2; h++)
                ldsm_x4_t(bf[h], bb + ks * 16 * BROW + ((b_nb + h * 32) ^ bSwzK));
#pragma unroll
            for (int mi = 0; mi < 8; mi++) {
                uint32_t a[4];
                ldsm_x4(a, aBase + mi * 16 * (KDIM * 2) +
                           (((c * KC * 2) + kB + a_kb) ^ aSwz));
#pragma unroll
                for (int ni = 0; ni < 4; ni++)
                    mma16816(acc[mi][ni], a, &bf[ni >> 1][(ni & 1) * 2]);
            }
        }
        __syncthreads();
        if (c + 2 < NCHUNK) { loadB(c & 1, (c + 2) * KC); cp_commit(); }
    }

    // ---- epilogue ----
    const int erow = lane >> 2;
    const int ecol = (lane & 3) * 2;
    if (EP == 2) {
#pragma unroll
        for (int mi = 0; mi < 8; mi++) {
#pragma unroll
            for (int h = 0; h < 2; h++) {
                const int m = wm + mi * 16 + h * 8 + erow;
                const float bv = bias[m];
                const size_t rb = ((size_t)(b * OCH + m)) * HWPX + p0;
#pragma unroll
                for (int ni = 0; ni < 4; ni++) {
                    const size_t o = rb + wp + ni * 8 + ecol;
                    float2 xr = *(const float2*)&xres[o];
                    float2 v;
                    v.x = acc[mi][ni][2 * h]     + bv + xr.x;
                    v.y = acc[mi][ni][2 * h + 1] + bv + xr.y;
                    *(float2*)&out[o] = v;
                }
            }
        }
    } else {
        float rs[8][2];
#pragma unroll
        for (int mi = 0; mi < 8; mi++) {
#pragma unroll
            for (int h = 0; h < 2; h++) {
                const int m = wm + mi * 16 + h * 8 + erow;
                const float bv = bias[m];
                float s2 = 0.f;
#pragma unroll
                for (int ni = 0; ni < 4; ni++) {
                    float v0 = fmaxf(acc[mi][ni][2 * h]     + bv, 0.f);
                    float v1 = fmaxf(acc[mi][ni][2 * h + 1] + bv, 0.f);
                    s2 += v0 + v1;
                    if (m < KSEL) {
                        size_t o = ((size_t)(b * KSEL + m)) * HWPX + p0 + wp + ni * 8 + ecol;
                        *(__nv_bfloat162*)&g_selb[o] = __floats2bfloat162_rn(v0, v1);
                    }
                }
                rs[mi][h] = s2;
            }
        }
#pragma unroll
        for (int mi = 0; mi < 8; mi++)
#pragma unroll
            for (int h = 0; h < 2; h++) {
                rs[mi][h] += __shfl_xor_sync(0xffffffffu, rs[mi][h], 1);
                rs[mi][h] += __shfl_xor_sync(0xffffffffu, rs[mi][h], 2);
            }
        if ((lane & 3) == 0) {
#pragma unroll
            for (int mi = 0; mi < 8; mi++)
#pragma unroll
                for (int h = 0; h < 2; h++)
                    sg[(wid & 3) * 256 + wm + mi * 16 + h * 8 + erow] = rs[mi][h];
        }
        __syncthreads();
        g_gap2_part[(b * MCH + t) * 128 + pc] =
            sg[t] + sg[256 + t] + sg[512 + t] + sg[768 + t];
    }
}

// =====================================================================
// k2a: gap (exact, from xmean) + gap2 partial reduce. grid 288.
// blocks 0..31: warp per m (8 batches). blocks 32..287: warp per (b,m) row.
// Per-output op order identical to R6 -> bit-identical results.
// =====================================================================
__global__ __launch_bounds__(256) void k2a(const float* __restrict__ pw1_w,
                                           const float* __restrict__ pw1_b)
{
    const int t = threadIdx.x, wid = t >> 5, lane = t & 31;
    if (blockIdx.x < 32) {
        __shared__ float sxm[2048];
        for (int i = t; i < 2048; i += 256) sxm[i] = gXmean[i];
        __syncthreads();
        const int m = blockIdx.x * 8 + wid;
        const float* wr = pw1_w + m * CIN;
        float acc[8] = {0.f, 0.f, 0.f, 0.f, 0.f, 0.f, 0.f, 0.f};
        for (int c = lane; c < CIN; c += 32) {
            float w = wr[c];
#pragma unroll
            for (int bb = 0; bb < 8; bb++) acc[bb] = fmaf(sxm[bb * 256 + c], w, acc[bb]);
        }
#pragma unroll
        for (int bb = 0; bb < 8; bb++) acc[bb] = wred(acc[bb]);
        if (lane == 0) {
            float bv = pw1_b[m];
#pragma unroll
            for (int bb = 0; bb < 8; bb++) g_gapv[bb * 256 + m] = acc[bb] + bv;
        }
    } else {
        const int rr = (blockIdx.x - 32) * 8 + wid;
        const float4* p4 = (const float4*)(g_gap2_part + (size_t)rr * 128);
        float4 v = p4[lane];
        float a = wred(v.x + v.y + v.z + v.w);
        if (lane == 0) g_gap2v[rr] = a * (1.f / (float)HWPX);
    }
}

// =====================================================================
// k2b: fc1 (512 outputs x 8 batches). grid 64, warp per j.
// =====================================================================
__global__ __launch_bounds__(256) void k2b(const float* __restrict__ fc1_w,
                                           const float* __restrict__ fc1_b)
{
    __shared__ float sgap[2048];
    const int t = threadIdx.x, wid = t >> 5, lane = t & 31;
    for (int i = t; i < 2048; i += 256) sgap[i] = g_gapv[i];
    __syncthreads();
    const int j = blockIdx.x * 8 + wid;
    const float* wr = fc1_w + j * MCH;
    float acc[8] = {0.f, 0.f, 0.f, 0.f, 0.f, 0.f, 0.f, 0.f};
    for (int c = lane; c < MCH; c += 32) {
        float w = wr[c];
#pragma unroll
        for (int bb = 0; bb < 8; bb++) acc[bb] = fmaf(sgap[bb * 256 + c], w, acc[bb]);
    }
#pragma unroll
    for (int bb = 0; bb < 8; bb++) acc[bb] = wred(acc[bb]);
    if (lane == 0) {
        float bv = fc1_b[j];
#pragma unroll
        for (int bb = 0; bb < 8; bb++) g_hidv[bb * 512 + j] = fmaxf(acc[bb] + bv, 0.f);
    }
}

// =====================================================================
// k2c: fc2 + sigmoid (256 outputs x 8 batches). grid 32, warp per j.
// =====================================================================
__global__ __launch_bounds__(256) void k2c(const float* __restrict__ fc2_w,
                                           const float* __restrict__ fc2_b)
{
    __shared__ float shid[4096];
    const int t = threadIdx.x, wid = t >> 5, lane = t & 31;
    for (int i = t; i < 4096; i += 256) shid[i] = g_hidv[i];
    __syncthreads();
    const int j = blockIdx.x * 8 + wid;
    const float* wr = fc2_w + j * 512;
    float acc[8] = {0.f, 0.f, 0.f, 0.f, 0.f, 0.f, 0.f, 0.f};
    for (int c = lane; c < 512; c += 32) {
        float w = wr[c];
#pragma unroll
        for (int bb = 0; bb < 8; bb++) acc[bb] = fmaf(shid[bb * 512 + c], w, acc[bb]);
    }
#pragma unroll
    for (int bb = 0; bb < 8; bb++) acc[bb] = wred(acc[bb]);
    if (lane == 0) {
        float bv = fc2_b[j];
#pragma unroll
        for (int bb = 0; bb < 8; bb++)
            g_scorev[bb * 256 + j] = 1.f / (1.f + expf(-(acc[bb] + bv)));
    }
}

// =====================================================================
// k2d: top-k mask + offsets (redundant per slice-block, deterministic)
// + effective depthwise weights. grid 64 = 8 batches x 8 slices.
// =====================================================================
__global__ __launch_bounds__(256) void k2d(const float* __restrict__ off_w,
                                           const float* __restrict__ off_b,
                                           const float* __restrict__ dw3,
                                           const float* __restrict__ dw5,
                                           const float* __restrict__ dw7)
{
    __shared__ float ssc[256], sg2[256], smask[128], sscl[3], ssht[3];
    const int t = threadIdx.x, wid = t >> 5, lane = t & 31;
    const int bb = blockIdx.x >> 3, slice = blockIdx.x & 7;

    ssc[t] = g_scorev[bb * 256 + t];
    sg2[t] = g_gap2v[bb * 256 + t];
    __syncthreads();

    if (wid < 6) {
        const int r = wid;
        const float* wr = off_w + r * MCH;
        float a = 0.f;
        for (int c = lane; c < MCH; c += 32) a = fmaf(sg2[c], wr[c], a);
        a = wred(a);
        if (lane == 0) {
            float o = tanhf(a + off_b[r]);
            if ((r & 1) == 0) sscl[r >> 1] = 1.f / (1.f + expf(-o));
            else              ssht[r >> 1] = tanhf(o);
        }
    }
    if (t < KSEL) {
        float sc = ssc[t];
        int cnt = 0;
        for (int j = 0; j < MCH; j++) {
            float sj = ssc[j];
            cnt += (sj > sc) || (sj == sc && j < t);
        }
        smask[t] = (cnt < KSEL) ? 1.f : 0.f;
    }
    __syncthreads();

    for (int i = slice * 256 + t; i < 1152; i += 2048) {
        int c = i / 9;
        g_w3[bb * 1152 + i] = fmaf(dw3[i], 1.f + sscl[0], ssht[0]) * smask[c];
    }
    for (int i = slice * 256 + t; i < 3200; i += 2048) {
        int c = i / 25;
        g_w5[bb * 3200 + i] = fmaf(dw5[i], 1.f + sscl[1], ssht[1]) * smask[c];
    }
    for (int i = slice * 256 + t; i < 6272; i += 2048) {
        int c = i / 49;
        g_w7[bb * 6272 + i] = fmaf(dw7[i], 1.f + sscl[2], ssht[2]) * smask[c];
    }
}

// =====================================================================
// k3: fused depthwise 3x3+5x5+7x7, bf16 in/out, fp32 compute
// =====================================================================
__global__ __launch_bounds__(256) void k3_dwconv()
{
    __shared__ float s[38][38];
    __shared__ float sw[84];

    const int b = blockIdx.z;
    const int c = blockIdx.y;
    const int tile = blockIdx.x;
    const int ty0 = (tile >> 2) * 32;
    const int tx0 = (tile & 3) * 32;
    const int t = threadIdx.x;

    const __nv_bfloat16* in = g_selb + ((size_t)(b * KSEL + c)) * HWPX;

    for (int i = t; i < 38 * 38; i += 256) {
        int r = i / 38, cc = i % 38;
        int gy = ty0 + r - 3, gx = tx0 + cc - 3;
        s[r][cc] = (gy >= 0 && gy < HH && gx >= 0 && gx < WW) ? __bfloat162float(in[gy * WW + gx]) : 0.f;
    }
    if (t < 9)        sw[t] = g_w3[(b * KSEL + c) * 9 + t];
    else if (t < 34)  sw[t] = g_w5[(b * KSEL + c) * 25 + (t - 9)];
    else if (t < 83)  sw[t] = g_w7[(b * KSEL + c) * 49 + (t - 34)];
    __syncthreads();

    for (int i = t; i < 1024; i += 256) {
        int py = i >> 5, px = i & 31;
        float a3 = 0.f, a5 = 0.f, a7 = 0.f;
#pragma unroll
        for (int dy = -3; dy <= 3; dy++) {
#pragma unroll
            for (int dx = -3; dx <= 3; dx++) {
                float v = s[py + 3 + dy][px + 3 + dx];
                a7 = fmaf(sw[34 + (dy + 3) * 7 + (dx + 3)], v, a7);
                if (dy >= -2 && dy <= 2 && dx >= -2 && dx <= 2)
                    a5 = fmaf(sw[9 + (dy + 2) * 5 + (dx + 2)], v, a5);
                if (dy >= -1 && dy <= 1 && dx >= -1 && dx <= 1)
                    a3 = fmaf(sw[(dy + 1) * 3 + (dx + 1)], v, a3);
            }
        }
        size_t o = ((size_t)(b * (3 * KSEL) + c)) * HWPX + (ty0 + py) * WW + tx0 + px;
        g_fusedb[o]                           = __float2bfloat16(a3);
        g_fusedb[o + (size_t)KSEL * HWPX]     = __float2bfloat16(a5);
        g_fusedb[o + (size_t)2 * KSEL * HWPX] = __float2bfloat16(a7);
    }
}

// =====================================================================
extern "C" void kernel_launch(void* const* d_in, const int* in_sizes, int n_in,
                              void* d_out, int out_size)
{
    const float* x     = (const float*)d_in[0];
    const float* pw1_w = (const float*)d_in[1];
    const float* pw1_b = (const float*)d_in[2];
    const float* fc1_w = (const float*)d_in[3];
    const float* fc1_b = (const float*)d_in[4];
    const float* fc2_w = (const float*)d_in[5];
    const float* fc2_b = (const float*)d_in[6];
    const float* off_w = (const float*)d_in[7];
    const float* off_b = (const float*)d_in[8];
    const float* dw3   = (const float*)d_in[9];
    const float* dw5   = (const float*)d_in[10];
    const float* dw7   = (const float*)d_in[11];
    const float* pw_w  = (const float*)d_in[12];
    const float* pw_b  = (const float*)d_in[13];
    float* out = (float*)d_out;

    const int smem1 = 256 * 256 * 2 + 2 * 16384 + 4 * 256 * 4 + 256;   // 168192
    const int smem2 = 256 * 384 * 2 + 2 * 16384 + 256;                  // 229632
    cudaFuncSetAttribute((const void*)kgemm<256, 1>, cudaFuncAttributeMaxDynamicSharedMemorySize, smem1);
    cudaFuncSetAttribute((const void*)kgemm<384, 2>, cudaFuncAttributeMaxDynamicSharedMemorySize, smem2);

    __nv_bfloat16 *gA1p, *gA2p, *gXbp, *gFbp;
    cudaGetSymbolAddress((void**)&gA1p, gA1);
    cudaGetSymbolAddress((void**)&gA2p, gA2);
    cudaGetSymbolAddress((void**)&gXbp, gXb);
    cudaGetSymbolAddress((void**)&gFbp, g_fusedb);

    kxc<<<BATCH * CIN, 256>>>(x);
    kprep<<<640, 256>>>(pw1_w, pw_w);
    kgemm<256, 1><<<dim3(128, 1, BATCH), 256, smem1>>>(gA1p, gXbp, pw1_b, nullptr, nullptr);
    k2a<<<288, 256>>>(pw1_w, pw1_b);
    k2b<<<64, 256>>>(fc1_w, fc1_b);
    k2c<<<32, 256>>>(fc2_w, fc2_b);
    k2d<<<64, 256>>>(off_w, off_b, dw3, dw5, dw7);
    k3_dwconv<<<dim3(16, KSEL, BATCH), 256>>>();
    kgemm<384, 2><<<dim3(128, 1, BATCH), 256, smem2>>>(gA2p, gFbp, pw_b, x, out);
}

// round 8
// speedup vs baseline: 4.6931x; 1.3904x over previous
#include <cuda_runtime.h>
#include <cuda_bf16.h>
#include <cstdint>
#include <math.h>

#define BATCH 8
#define CIN   256
#define MCH   256
#define OCH   256
#define HH    128
#define WW    128
#define HWPX  16384
#define KSEL  128

// ---------------- device scratch ----------------
__device__ __align__(128) __nv_bfloat16 gXb[(size_t)BATCH * CIN * HWPX];           // x bf16
__device__ __align__(128) __nv_bfloat16 g_selb[(size_t)BATCH * KSEL * HWPX];       // relu(h)[:,:128] bf16
__device__ __align__(128) __nv_bfloat16 g_fusedb[(size_t)BATCH * 3 * KSEL * HWPX]; // dwconv out bf16
__device__ __align__(128) __nv_bfloat16 gA1[256 * 256];                            // pw1_w bf16 linear
__device__ __align__(128) __nv_bfloat16 gA2[256 * 384];                            // pw_w[:, :384] bf16 linear
__device__ float gXmean[BATCH * CIN];
__device__ float g_gap2_part[BATCH * MCH * 128];
__device__ float g_gapv[BATCH * MCH];
__device__ float g_gap2v[BATCH * MCH];
__device__ float g_hidv[BATCH * 512];
__device__ float g_scorev[BATCH * MCH];
__device__ float g_w3[BATCH * KSEL * 9];
__device__ float g_w5[BATCH * KSEL * 25];
__device__ float g_w7[BATCH * KSEL * 49];

// ---------------- PTX helpers (baseline compute_103 features only) ----------------
__device__ __forceinline__ uint32_t smem_u32(const void* p) {
    uint32_t a;
    asm("{ .reg .u64 t; cvta.to.shared.u64 t, %1; cvt.u32.u64 %0, t; }" : "=r"(a) : "l"(p));
    return a;
}
__device__ __forceinline__ void cp16(uint32_t dst, const void* src) {
    asm volatile("cp.async.cg.shared.global [%0], [%1], 16;" :: "r"(dst), "l"(src) : "memory");
}
__device__ __forceinline__ void cp_commit() { asm volatile("cp.async.commit_group;" ::: "memory"); }
template<int N> __device__ __forceinline__ void cp_wait() { asm volatile("cp.async.wait_group %0;" :: "n"(N) : "memory"); }

__device__ __forceinline__ void ldsm_x4(uint32_t* r, uint32_t addr) {
    asm volatile("ldmatrix.sync.aligned.m8n8.x4.shared.b16 {%0,%1,%2,%3}, [%4];"
                 : "=r"(r[0]), "=r"(r[1]), "=r"(r[2]), "=r"(r[3]) : "r"(addr));
}
__device__ __forceinline__ void ldsm_x4_t(uint32_t* r, uint32_t addr) {
    asm volatile("ldmatrix.sync.aligned.m8n8.x4.trans.shared.b16 {%0,%1,%2,%3}, [%4];"
                 : "=r"(r[0]), "=r"(r[1]), "=r"(r[2]), "=r"(r[3]) : "r"(addr));
}
__device__ __forceinline__ void mma16816(float* d, const uint32_t* a, const uint32_t* b) {
    asm volatile("mma.sync.aligned.m16n8k16.row.col.f32.bf16.bf16.f32 "
                 "{%0,%1,%2,%3}, {%4,%5,%6,%7}, {%8,%9}, {%0,%1,%2,%3};"
                 : "+f"(d[0]), "+f"(d[1]), "+f"(d[2]), "+f"(d[3])
                 : "r"(a[0]), "r"(a[1]), "r"(a[2]), "r"(a[3]), "r"(b[0]), "r"(b[1]));
}
__device__ __forceinline__ float wred(float v) {
    v += __shfl_xor_sync(0xffffffffu, v, 16);
    v += __shfl_xor_sync(0xffffffffu, v, 8);
    v += __shfl_xor_sync(0xffffffffu, v, 4);
    v += __shfl_xor_sync(0xffffffffu, v, 2);
    v += __shfl_xor_sync(0xffffffffu, v, 1);
    return v;
}

// =====================================================================
// kxc: x fp32 -> bf16 + exact fp32 row means (score path stays exact)
// =====================================================================
__global__ __launch_bounds__(256) void kxc(const float* __restrict__ x)
{
    __shared__ float red[256];
    const int row = blockIdx.x;
    const int t = threadIdx.x;
    const float4* in4 = (const float4*)(x + (size_t)row * HWPX);
    __nv_bfloat162* ob = (__nv_bfloat162*)(gXb + (size_t)row * HWPX);
    float s = 0.f;
#pragma unroll
    for (int it = 0; it < 16; it++) {
        int j = t + it * 256;
        float4 v = in4[j];
        s += v.x + v.y + v.z + v.w;
        ob[j * 2 + 0] = __floats2bfloat162_rn(v.x, v.y);
        ob[j * 2 + 1] = __floats2bfloat162_rn(v.z, v.w);
    }
    red[t] = s;
    __syncthreads();
    for (int o = 128; o > 0; o >>= 1) {
        if (t < o) red[t] += red[t + o];
        __syncthreads();
    }
    if (t == 0) gXmean[row] = red[0] * (1.f / (float)HWPX);
}

// =====================================================================
// kprep: weights -> bf16 linear row-major images
// =====================================================================
__global__ __launch_bounds__(256) void kprep(const float* __restrict__ pw1_w,
                                             const float* __restrict__ pw_w)
{
    int i = blockIdx.x * 256 + threadIdx.x;
    if (i < 65536) {
        gA1[i] = __float2bfloat16(pw1_w[i]);
    } else {
        int j = i - 65536;            // 256 rows x 384 cols
        int m = j / 384, k = j % 384;
        gA2[j] = __float2bfloat16(pw_w[m * 768 + k]);
    }
}

// =====================================================================
// kgemm<KDIM, EP> (M=256 merged): mma.sync bf16 GEMM.
// CTA 256m x 128p, 8 warps (2x4), warp tile 128m x 32p.
// grid (128, 1, BATCH), 256 threads.
// =====================================================================
template<int KDIM, int EP>
__global__ __launch_bounds__(256, 1)
void kgemm(const __nv_bfloat16* __restrict__ Aimg,
           const __nv_bfloat16* __restrict__ Bsrc,
           const float* __restrict__ bias,
           const float* __restrict__ xres,
           float* __restrict__ out)
{
    constexpr int KC = 64;
    constexpr int NCHUNK = KDIM / KC;
    constexpr int ASZ = 256 * KDIM * 2;      // bytes (256 m-rows)
    constexpr int BROW = 256;                // bytes per B k-row (128 bf16)
    constexpr int BSZ = KC * BROW;           // 16KB per buffer

    extern __shared__ char sraw[];
    const uint32_t rawu = smem_u32(sraw);
    const uint32_t sbase = (rawu + 127u) & ~127u;
    const uint32_t uA = sbase;
    const uint32_t uB = sbase + ASZ;
    float* sg = (float*)(sraw + (sbase - rawu) + ASZ + 2 * BSZ);   // [4][256] (EP1)

    const int t = threadIdx.x, wid = t >> 5, lane = t & 31;
    const int b = blockIdx.z, pc = blockIdx.x;
    const int p0 = pc * 128;
    const int wm = (wid >> 2) * 128;         // warp m offset (0 or 128)
    const int wp = (wid & 3) * 32;           // warp p offset

    const char* Bb = (const char*)(Bsrc + (size_t)b * KDIM * HWPX);
    const char* Ab = (const char*)Aimg;

    // ---- A load (swizzled), full 256 x K ----
    {
        constexpr int CPR = KDIM / 8;        // 16B chunks per row
        for (int i = t; i < 256 * CPR; i += 256) {
            int m = i / CPR, j = i % CPR;
            cp16(uA + m * (KDIM * 2) + ((j * 16) ^ ((m & 7) << 4)),
                 Ab + (size_t)m * (KDIM * 2) + j * 16);
        }
    }
    // ---- B chunk loader ----
    auto loadB = [&](int buf, int kc0) {
        uint32_t dst = uB + buf * BSZ;
#pragma unroll
        for (int i = t; i < KC * 16; i += 256) {
            int k = i >> 4, j = i & 15;
            cp16(dst + k * BROW + ((j * 16) ^ ((k & 7) << 4)),
                 Bb + ((size_t)(kc0 + k) * HWPX + p0) * 2 + j * 16);
        }
    };
    loadB(0, 0);
    cp_commit();                 // group0: A + B0
    if (NCHUNK > 1) { loadB(1, KC); cp_commit(); }

    float acc[8][4][4];
#pragma unroll
    for (int mi = 0; mi < 8; mi++)
#pragma unroll
        for (int ni = 0; ni < 4; ni++)
#pragma unroll
            for (int r = 0; r < 4; r++) acc[mi][ni][r] = 0.f;

    // precomputed lane addresses
    const int a_m  = wm + (lane & 15);
    const int a_kb = (lane >> 4) * 16;                 // byte offset for k-half
    const uint32_t aBase = uA + a_m * (KDIM * 2);
    const uint32_t aSwz  = (a_m & 7) << 4;
    const int b_k  = lane & 15;
    const int b_nb = wp * 2 + (lane >> 4) * 16;        // byte offset of n within row
    const uint32_t bSwzK = (b_k & 7) << 4;

    for (int c = 0; c < NCHUNK; c++) {
        // on the final chunk the only outstanding group holds this chunk's
        // data — drain fully there (race fix, R4, protected).
        if (c == NCHUNK - 1) cp_wait<0>(); else cp_wait<1>();
        __syncthreads();
        const uint32_t bb = uB + (c & 1) * BSZ + b_k * BROW;
#pragma unroll
        for (int ks = 0; ks < KC / 16; ks++) {
            const int kB = ks * 32;                    // byte offset of k within chunk
            uint32_t bf[2][4];
#pragma unroll
            for (int h = 0; h < 2; h++)
                ldsm_x4_t(bf[h], bb + ks * 16 * BROW + ((b_nb + h * 32) ^ bSwzK));
#pragma unroll
            for (int mi = 0; mi < 8; mi++) {
                uint32_t a[4];
                ldsm_x4(a, aBase + mi * 16 * (KDIM * 2) +
                           (((c * KC * 2) + kB + a_kb) ^ aSwz));
#pragma unroll
                for (int ni = 0; ni < 4; ni++)
                    mma16816(acc[mi][ni], a, &bf[ni >> 1][(ni & 1) * 2]);
            }
        }
        __syncthreads();
        if (c + 2 < NCHUNK) { loadB(c & 1, (c + 2) * KC); cp_commit(); }
    }

    // ---- epilogue ----
    const int erow = lane >> 2;
    const int ecol = (lane & 3) * 2;
    if (EP == 2) {
#pragma unroll
        for (int mi = 0; mi < 8; mi++) {
#pragma unroll
            for (int h = 0; h < 2; h++) {
                const int m = wm + mi * 16 + h * 8 + erow;
                const float bv = bias[m];
                const size_t rb = ((size_t)(b * OCH + m)) * HWPX + p0;
#pragma unroll
                for (int ni = 0; ni < 4; ni++) {
                    const size_t o = rb + wp + ni * 8 + ecol;
                    float2 xr = *(const float2*)&xres[o];
                    float2 v;
                    v.x = acc[mi][ni][2 * h]     + bv + xr.x;
                    v.y = acc[mi][ni][2 * h + 1] + bv + xr.y;
                    *(float2*)&out[o] = v;
                }
            }
        }
    } else {
        float rs[8][2];
#pragma unroll
        for (int mi = 0; mi < 8; mi++) {
#pragma unroll
            for (int h = 0; h < 2; h++) {
                const int m = wm + mi * 16 + h * 8 + erow;
                const float bv = bias[m];
                float s2 = 0.f;
#pragma unroll
                for (int ni = 0; ni < 4; ni++) {
                    float v0 = fmaxf(acc[mi][ni][2 * h]     + bv, 0.f);
                    float v1 = fmaxf(acc[mi][ni][2 * h + 1] + bv, 0.f);
                    s2 += v0 + v1;
                    if (m < KSEL) {
                        size_t o = ((size_t)(b * KSEL + m)) * HWPX + p0 + wp + ni * 8 + ecol;
                        *(__nv_bfloat162*)&g_selb[o] = __floats2bfloat162_rn(v0, v1);
                    }
                }
                rs[mi][h] = s2;
            }
        }
#pragma unroll
        for (int mi = 0; mi < 8; mi++)
#pragma unroll
            for (int h = 0; h < 2; h++) {
                rs[mi][h] += __shfl_xor_sync(0xffffffffu, rs[mi][h], 1);
                rs[mi][h] += __shfl_xor_sync(0xffffffffu, rs[mi][h], 2);
            }
        if ((lane & 3) == 0) {
#pragma unroll
            for (int mi = 0; mi < 8; mi++)
#pragma unroll
                for (int h = 0; h < 2; h++)
                    sg[(wid & 3) * 256 + wm + mi * 16 + h * 8 + erow] = rs[mi][h];
        }
        __syncthreads();
        g_gap2_part[(b * MCH + t) * 128 + pc] =
            sg[t] + sg[256 + t] + sg[512 + t] + sg[768 + t];
    }
}

// =====================================================================
// k2a: gap (exact, from xmean) + gap2 partial reduce. grid 288.
// =====================================================================
__global__ __launch_bounds__(256) void k2a(const float* __restrict__ pw1_w,
                                           const float* __restrict__ pw1_b)
{
    const int t = threadIdx.x, wid = t >> 5, lane = t & 31;
    if (blockIdx.x < 32) {
        __shared__ float sxm[2048];
        for (int i = t; i < 2048; i += 256) sxm[i] = gXmean[i];
        __syncthreads();
        const int m = blockIdx.x * 8 + wid;
        const float* wr = pw1_w + m * CIN;
        float acc[8] = {0.f, 0.f, 0.f, 0.f, 0.f, 0.f, 0.f, 0.f};
        for (int c = lane; c < CIN; c += 32) {
            float w = wr[c];
#pragma unroll
            for (int bb = 0; bb < 8; bb++) acc[bb] = fmaf(sxm[bb * 256 + c], w, acc[bb]);
        }
#pragma unroll
        for (int bb = 0; bb < 8; bb++) acc[bb] = wred(acc[bb]);
        if (lane == 0) {
            float bv = pw1_b[m];
#pragma unroll
            for (int bb = 0; bb < 8; bb++) g_gapv[bb * 256 + m] = acc[bb] + bv;
        }
    } else {
        const int rr = (blockIdx.x - 32) * 8 + wid;
        const float4* p4 = (const float4*)(g_gap2_part + (size_t)rr * 128);
        float4 v = p4[lane];
        float a = wred(v.x + v.y + v.z + v.w);
        if (lane == 0) g_gap2v[rr] = a * (1.f / (float)HWPX);
    }
}

// =====================================================================
// k2b: fc1 (512 outputs x 8 batches). grid 64, warp per j.
// =====================================================================
__global__ __launch_bounds__(256) void k2b(const float* __restrict__ fc1_w,
                                           const float* __restrict__ fc1_b)
{
    __shared__ float sgap[2048];
    const int t = threadIdx.x, wid = t >> 5, lane = t & 31;
    for (int i = t; i < 2048; i += 256) sgap[i] = g_gapv[i];
    __syncthreads();
    const int j = blockIdx.x * 8 + wid;
    const float* wr = fc1_w + j * MCH;
    float acc[8] = {0.f, 0.f, 0.f, 0.f, 0.f, 0.f, 0.f, 0.f};
    for (int c = lane; c < MCH; c += 32) {
        float w = wr[c];
#pragma unroll
        for (int bb = 0; bb < 8; bb++) acc[bb] = fmaf(sgap[bb * 256 + c], w, acc[bb]);
    }
#pragma unroll
    for (int bb = 0; bb < 8; bb++) acc[bb] = wred(acc[bb]);
    if (lane == 0) {
        float bv = fc1_b[j];
#pragma unroll
        for (int bb = 0; bb < 8; bb++) g_hidv[bb * 512 + j] = fmaxf(acc[bb] + bv, 0.f);
    }
}

// =====================================================================
// k2c: fc2 + sigmoid (256 outputs x 8 batches). grid 32, warp per j.
// =====================================================================
__global__ __launch_bounds__(256) void k2c(const float* __restrict__ fc2_w,
                                           const float* __restrict__ fc2_b)
{
    __shared__ float shid[4096];
    const int t = threadIdx.x, wid = t >> 5, lane = t & 31;
    for (int i = t; i < 4096; i += 256) shid[i] = g_hidv[i];
    __syncthreads();
    const int j = blockIdx.x * 8 + wid;
    const float* wr = fc2_w + j * 512;
    float acc[8] = {0.f, 0.f, 0.f, 0.f, 0.f, 0.f, 0.f, 0.f};
    for (int c = lane; c < 512; c += 32) {
        float w = wr[c];
#pragma unroll
        for (int bb = 0; bb < 8; bb++) acc[bb] = fmaf(shid[bb * 512 + c], w, acc[bb]);
    }
#pragma unroll
    for (int bb = 0; bb < 8; bb++) acc[bb] = wred(acc[bb]);
    if (lane == 0) {
        float bv = fc2_b[j];
#pragma unroll
        for (int bb = 0; bb < 8; bb++)
            g_scorev[bb * 256 + j] = 1.f / (1.f + expf(-(acc[bb] + bv)));
    }
}

// =====================================================================
// k2d: top-k mask + offsets + effective depthwise weights. grid 64.
// =====================================================================
__global__ __launch_bounds__(256) void k2d(const float* __restrict__ off_w,
                                           const float* __restrict__ off_b,
                                           const float* __restrict__ dw3,
                                           const float* __restrict__ dw5,
                                           const float* __restrict__ dw7)
{
    __shared__ float ssc[256], sg2[256], smask[128], sscl[3], ssht[3];
    const int t = threadIdx.x, wid = t >> 5, lane = t & 31;
    const int bb = blockIdx.x >> 3, slice = blockIdx.x & 7;

    ssc[t] = g_scorev[bb * 256 + t];
    sg2[t] = g_gap2v[bb * 256 + t];
    __syncthreads();

    if (wid < 6) {
        const int r = wid;
        const float* wr = off_w + r * MCH;
        float a = 0.f;
        for (int c = lane; c < MCH; c += 32) a = fmaf(sg2[c], wr[c], a);
        a = wred(a);
        if (lane == 0) {
            float o = tanhf(a + off_b[r]);
            if ((r & 1) == 0) sscl[r >> 1] = 1.f / (1.f + expf(-o));
            else              ssht[r >> 1] = tanhf(o);
        }
    }
    if (t < KSEL) {
        float sc = ssc[t];
        int cnt = 0;
        for (int j = 0; j < MCH; j++) {
            float sj = ssc[j];
            cnt += (sj > sc) || (sj == sc && j < t);
        }
        smask[t] = (cnt < KSEL) ? 1.f : 0.f;
    }
    __syncthreads();

    for (int i = slice * 256 + t; i < 1152; i += 2048) {
        int c = i / 9;
        g_w3[bb * 1152 + i] = fmaf(dw3[i], 1.f + sscl[0], ssht[0]) * smask[c];
    }
    for (int i = slice * 256 + t; i < 3200; i += 2048) {
        int c = i / 25;
        g_w5[bb * 3200 + i] = fmaf(dw5[i], 1.f + sscl[1], ssht[1]) * smask[c];
    }
    for (int i = slice * 256 + t; i < 6272; i += 2048) {
        int c = i / 49;
        g_w7[bb * 6272 + i] = fmaf(dw7[i], 1.f + sscl[2], ssht[2]) * smask[c];
    }
}

// =====================================================================
// k3 (R8): fused depthwise 3x3+5x5+7x7, vectorized LDS.
// Each thread computes 4 x-adjacent pixels; per dy row loads the 12-float
// window as 3 x float4 (rows padded to 40 floats for 16B alignment).
// Per-accumulator (dy,dx) order identical to R7 -> bit-identical output.
// =====================================================================
__global__ __launch_bounds__(256) void k3_dwconv()
{
    __shared__ float s[38][40];
    __shared__ float sw[84];

    const int b = blockIdx.z;
    const int c = blockIdx.y;
    const int tile = blockIdx.x;
    const int ty0 = (tile >> 2) * 32;
    const int tx0 = (tile & 3) * 32;
    const int t = threadIdx.x;

    const __nv_bfloat16* in = g_selb + ((size_t)(b * KSEL + c)) * HWPX;

    for (int i = t; i < 38 * 38; i += 256) {
        int r = i / 38, cc = i % 38;
        int gy = ty0 + r - 3, gx = tx0 + cc - 3;
        s[r][cc] = (gy >= 0 && gy < HH && gx >= 0 && gx < WW) ? __bfloat162float(in[gy * WW + gx]) : 0.f;
    }
    if (t < 9)        sw[t] = g_w3[(b * KSEL + c) * 9 + t];
    else if (t < 34)  sw[t] = g_w5[(b * KSEL + c) * 25 + (t - 9)];
    else if (t < 83)  sw[t] = g_w7[(b * KSEL + c) * 49 + (t - 34)];
    __syncthreads();

    const int py  = t >> 3;          // 0..31
    const int px0 = (t & 7) * 4;     // 0,4,...,28

    float a3[4] = {0.f, 0.f, 0.f, 0.f};
    float a5[4] = {0.f, 0.f, 0.f, 0.f};
    float a7[4] = {0.f, 0.f, 0.f, 0.f};

#pragma unroll
    for (int dy = 0; dy < 7; dy++) {
        const float* row = &s[py + dy][0];
        float4 v0 = *(const float4*)&row[px0];
        float4 v1 = *(const float4*)&row[px0 + 4];
        float4 v2 = *(const float4*)&row[px0 + 8];
        float w[12] = {v0.x, v0.y, v0.z, v0.w, v1.x, v1.y, v1.z, v1.w,
                       v2.x, v2.y, v2.z, v2.w};
        // 7x7: all rows; local col = j + dx7
#pragma unroll
        for (int dx = 0; dx < 7; dx++) {
            float wt = sw[34 + dy * 7 + dx];
#pragma unroll
            for (int j = 0; j < 4; j++) a7[j] = fmaf(w[j + dx], wt, a7[j]);
        }
        // 5x5: rows 1..5; local col = j + 1 + dx5
        if (dy >= 1 && dy <= 5) {
#pragma unroll
            for (int dx = 0; dx < 5; dx++) {
                float wt = sw[9 + (dy - 1) * 5 + dx];
#pragma unroll
                for (int j = 0; j < 4; j++) a5[j] = fmaf(w[j + 1 + dx], wt, a5[j]);
            }
        }
        // 3x3: rows 2..4; local col = j + 2 + dx3
        if (dy >= 2 && dy <= 4) {
#pragma unroll
            for (int dx = 0; dx < 3; dx++) {
                float wt = sw[(dy - 2) * 3 + dx];
#pragma unroll
                for (int j = 0; j < 4; j++) a3[j] = fmaf(w[j + 2 + dx], wt, a3[j]);
            }
        }
    }

    size_t o = ((size_t)(b * (3 * KSEL) + c)) * HWPX + (ty0 + py) * WW + tx0 + px0;
    {
        __nv_bfloat162 p0 = __floats2bfloat162_rn(a3[0], a3[1]);
        __nv_bfloat162 p1 = __floats2bfloat162_rn(a3[2], a3[3]);
        *(uint2*)&g_fusedb[o] = make_uint2(*(uint32_t*)&p0, *(uint32_t*)&p1);
        p0 = __floats2bfloat162_rn(a5[0], a5[1]);
        p1 = __floats2bfloat162_rn(a5[2], a5[3]);
        *(uint2*)&g_fusedb[o + (size_t)KSEL * HWPX] = make_uint2(*(uint32_t*)&p0, *(uint32_t*)&p1);
        p0 = __floats2bfloat162_rn(a7[0], a7[1]);
        p1 = __floats2bfloat162_rn(a7[2], a7[3]);
        *(uint2*)&g_fusedb[o + (size_t)2 * KSEL * HWPX] = make_uint2(*(uint32_t*)&p0, *(uint32_t*)&p1);
    }
}

// =====================================================================
extern "C" void kernel_launch(void* const* d_in, const int* in_sizes, int n_in,
                              void* d_out, int out_size)
{
    const float* x     = (const float*)d_in[0];
    const float* pw1_w = (const float*)d_in[1];
    const float* pw1_b = (const float*)d_in[2];
    const float* fc1_w = (const float*)d_in[3];
    const float* fc1_b = (const float*)d_in[4];
    const float* fc2_w = (const float*)d_in[5];
    const float* fc2_b = (const float*)d_in[6];
    const float* off_w = (const float*)d_in[7];
    const float* off_b = (const float*)d_in[8];
    const float* dw3   = (const float*)d_in[9];
    const float* dw5   = (const float*)d_in[10];
    const float* dw7   = (const float*)d_in[11];
    const float* pw_w  = (const float*)d_in[12];
    const float* pw_b  = (const float*)d_in[13];
    float* out = (float*)d_out;

    const int smem1 = 256 * 256 * 2 + 2 * 16384 + 4 * 256 * 4 + 256;   // 168192
    const int smem2 = 256 * 384 * 2 + 2 * 16384 + 256;                  // 229632
    cudaFuncSetAttribute((const void*)kgemm<256, 1>, cudaFuncAttributeMaxDynamicSharedMemorySize, smem1);
    cudaFuncSetAttribute((const void*)kgemm<384, 2>, cudaFuncAttributeMaxDynamicSharedMemorySize, smem2);

    __nv_bfloat16 *gA1p, *gA2p, *gXbp, *gFbp;
    cudaGetSymbolAddress((void**)&gA1p, gA1);
    cudaGetSymbolAddress((void**)&gA2p, gA2);
    cudaGetSymbolAddress((void**)&gXbp, gXb);
    cudaGetSymbolAddress((void**)&gFbp, g_fusedb);

    kxc<<<BATCH * CIN, 256>>>(x);
    kprep<<<640, 256>>>(pw1_w, pw_w);
    kgemm<256, 1><<<dim3(128, 1, BATCH), 256, smem1>>>(gA1p, gXbp, pw1_b, nullptr, nullptr);
    k2a<<<288, 256>>>(pw1_w, pw1_b);
    k2b<<<64, 256>>>(fc1_w, fc1_b);
    k2c<<<32, 256>>>(fc2_w, fc2_b);
    k2d<<<64, 256>>>(off_w, off_b, dw3, dw5, dw7);
    k3_dwconv<<<dim3(16, KSEL, BATCH), 256>>>();
    kgemm<384, 2><<<dim3(128, 1, BATCH), 256, smem2>>>(gA2p, gFbp, pw_b, x, out);
}